// round 5
// baseline (speedup 1.0000x reference)
#include <cuda_runtime.h>
#include <math.h>
#include <stdint.h>

// ---------------- fixed shapes ----------------
#define TKN   4096          // B*L tokens
#define NB    2
#define LSEQ  2048
#define DM    4096          // d_model
#define DXB   1024
#define DIN   4096          // d_inner
#define NH    32            // heads
#define HP    128           // headdim P
#define HN    128           // dstate N
#define PROJ  10272         // 2*DIN + 2*DXB + NH
#define CONVD 6144          // 2*DXB + DIN
#define INTERD 14336
#define NCH   16            // chunks per batch (2048/128)
#define NBLK  (NB*NCH*NH)   // 1024 ssd blocks

// ---------------- scratch (static device globals; no allocations) ----------------
__device__ float d_hnorm[TKN*DM];
__device__ float d_zx[TKN*PROJ];
__device__ float d_xbc[TKN*CONVD];
__device__ float d_dt[TKN*NH];
__device__ float d_av[TKN*NH];
__device__ float d_cs[NBLK*128];
__device__ float d_gm[NBLK];
__device__ float d_states[(size_t)NBLK*HP*HN];
__device__ float d_prev[(size_t)NBLK*HP*HN];
__device__ float d_Y[TKN*DIN];
__device__ float d_h[TKN*DM];
__device__ float d_h2[TKN*DM];
__device__ float d_ga[(size_t)TKN*INTERD];
__device__ float d_up[(size_t)TKN*INTERD];

// tf32 round-to-nearest helpers
static __device__ __forceinline__ float tf32r(float x) {
    uint32_t u; asm("cvt.rna.tf32.f32 %0, %1;" : "=r"(u) : "f"(x));
    return __uint_as_float(u);
}
static __device__ __forceinline__ uint32_t cvt_tf32(float x) {
    uint32_t u; asm("cvt.rna.tf32.f32 %0, %1;" : "=r"(u) : "f"(x));
    return u;
}

// ================= tf32 mma.sync GEMM =================
// C[M,N] = A[M,K] @ B[N,K]^T (+Res). M mult of 128, K mult of 32.
// CTA tile 128(M) x 256(N), BK=32, 3-stage cp.async pipeline, 8 warps (2m x 4n),
// warp tile 64x64. Grouped 1-D rasterization (GROUP_M=8) for L2 reuse.
// A is tf32-rounded at producers; B rounded in-register after ldmatrix.

#define GSTAGE 49152
#define GSMEM_DYN (3*GSTAGE)
#define GROUP_M 8

__global__ void __launch_bounds__(256, 1)
gemm_mma(const float* __restrict__ A, const float* __restrict__ Bw,
         const float* __restrict__ Res, float* __restrict__ C,
         int N, int K)
{
    extern __shared__ char smraw[];
    const int tid  = threadIdx.x;
    const int lane = tid & 31, warp = tid >> 5;
    const int wm = warp & 1, wn = warp >> 1;        // 2 x 4 warp grid
    const int T = K >> 5;
    uint32_t sbase = (uint32_t)__cvta_generic_to_shared(smraw);

    // grouped rasterization
    const int num_pid_m = 32;                       // M = 4096 fixed
    const int num_pid_n = (N + 255) >> 8;
    int pid = blockIdx.x;
    int npg = GROUP_M * num_pid_n;
    int group_id = pid / npg;
    int first_m = group_id * GROUP_M;
    int gsm = num_pid_m - first_m; if (gsm > GROUP_M) gsm = GROUP_M;
    int pid_m = first_m + (pid % gsm);
    int pid_n = (pid % npg) / gsm;
    const int bm = pid_m << 7, bn = pid_n << 8;

    // stage layout: A 16KB (128 rows x 128B), B 32KB (256 rows x 128B), 16B-swizzled
    auto load_tile = [&](int t) {
        uint32_t s = sbase + (uint32_t)(t % 3) * GSTAGE;
        int k0 = t << 5;
        #pragma unroll
        for (int i = 0; i < 4; i++) {
            int idx = i*256 + tid, row = idx >> 3, c = idx & 7;
            uint32_t dst = s + row*128 + (uint32_t)((c ^ (row & 7)) << 4);
            asm volatile("cp.async.cg.shared.global [%0], [%1], 16;"
                         :: "r"(dst), "l"(A + (size_t)(bm + row)*K + k0 + c*4));
        }
        #pragma unroll
        for (int i = 0; i < 8; i++) {
            int idx = i*256 + tid, row = idx >> 3, c = idx & 7;
            int brow = bn + row; if (brow >= N) brow = N - 1;
            uint32_t dst = s + 16384u + row*128 + (uint32_t)((c ^ (row & 7)) << 4);
            asm volatile("cp.async.cg.shared.global [%0], [%1], 16;"
                         :: "r"(dst), "l"(Bw + (size_t)brow*K + k0 + c*4));
        }
    };

    float acc[4][8][4];
    #pragma unroll
    for (int a = 0; a < 4; a++)
        #pragma unroll
        for (int b = 0; b < 8; b++)
            #pragma unroll
            for (int c = 0; c < 4; c++) acc[a][b][c] = 0.f;

    load_tile(0);
    asm volatile("cp.async.commit_group;" ::: "memory");
    load_tile(1);
    asm volatile("cp.async.commit_group;" ::: "memory");

    for (int t = 0; t < T; t++) {
        if (t + 2 < T) load_tile(t + 2);
        asm volatile("cp.async.commit_group;" ::: "memory");
        asm volatile("cp.async.wait_group 2;" ::: "memory");
        __syncthreads();

        uint32_t as = sbase + (uint32_t)(t % 3) * GSTAGE;
        uint32_t bs = as + 16384u;

        #pragma unroll
        for (int kk = 0; kk < 4; kk++) {
            // A fragments: 4 m-tiles via ldmatrix.x4
            uint32_t af[4][4];
            #pragma unroll
            for (int mt = 0; mt < 4; mt++) {
                int m  = wm*64 + mt*16 + (lane & 7) + ((lane >> 3) & 1) * 8;
                int kc = kk*2 + (lane >> 4);
                uint32_t addr = as + m*128 + (uint32_t)((kc ^ (m & 7)) << 4);
                asm volatile("ldmatrix.sync.aligned.m8n8.x4.shared.b16 {%0,%1,%2,%3}, [%4];"
                             : "=r"(af[mt][0]), "=r"(af[mt][1]),
                               "=r"(af[mt][2]), "=r"(af[mt][3]) : "r"(addr));
            }
            #pragma unroll
            for (int nt = 0; nt < 8; nt++) {
                // B pair (b0,b1) via one ldmatrix.x2: lanes 0-7 -> chunk 2kk,
                // lanes 8-15 -> chunk 2kk+1, rows = n
                int nrow = wn*64 + nt*8 + (lane & 7);
                int bc = kk*2 + ((lane >> 3) & 1);
                uint32_t baddr = bs + nrow*128 + (uint32_t)((bc ^ (nrow & 7)) << 4);
                uint32_t braw0, braw1;
                asm volatile("ldmatrix.sync.aligned.m8n8.x2.shared.b16 {%0,%1}, [%2];"
                             : "=r"(braw0), "=r"(braw1) : "r"(baddr));
                uint32_t b0 = cvt_tf32(__uint_as_float(braw0));
                uint32_t b1 = cvt_tf32(__uint_as_float(braw1));
                #pragma unroll
                for (int mt = 0; mt < 4; mt++) {
                    asm volatile(
                        "mma.sync.aligned.m16n8k8.row.col.f32.tf32.tf32.f32 "
                        "{%0,%1,%2,%3}, {%4,%5,%6,%7}, {%8,%9}, {%0,%1,%2,%3};"
                        : "+f"(acc[mt][nt][0]), "+f"(acc[mt][nt][1]),
                          "+f"(acc[mt][nt][2]), "+f"(acc[mt][nt][3])
                        : "r"(af[mt][0]), "r"(af[mt][1]), "r"(af[mt][2]), "r"(af[mt][3]),
                          "r"(b0), "r"(b1));
                }
            }
        }
        __syncthreads();
    }

    // epilogue
    #pragma unroll
    for (int mt = 0; mt < 4; mt++) {
        int r0 = bm + wm*64 + mt*16 + (lane >> 2);
        #pragma unroll
        for (int nt = 0; nt < 8; nt++) {
            int c0 = bn + wn*64 + nt*8 + 2*(lane & 3);
            if (c0 < N) {
                float2 v0 = make_float2(acc[mt][nt][0], acc[mt][nt][1]);
                float2 v1 = make_float2(acc[mt][nt][2], acc[mt][nt][3]);
                if (Res) {
                    float2 q0 = *reinterpret_cast<const float2*>(Res + (size_t)r0*N + c0);
                    float2 q1 = *reinterpret_cast<const float2*>(Res + (size_t)(r0+8)*N + c0);
                    v0.x += q0.x; v0.y += q0.y; v1.x += q1.x; v1.y += q1.y;
                }
                *reinterpret_cast<float2*>(C + (size_t)r0*N + c0)     = v0;
                *reinterpret_cast<float2*>(C + (size_t)(r0+8)*N + c0) = v1;
            }
        }
    }
}

static inline int gemm_grid(int N) { return 32 * ((N + 255) >> 8); }

// ---------------- RMSNorm (output tf32-rounded: feeds GEMM A operands) ----------------
__global__ void rmsnorm_k(const float* __restrict__ x, const float* __restrict__ w,
                          float* __restrict__ o)
{
    int t = blockIdx.x;
    const float* xr = x + (size_t)t*DM;
    float s = 0.f;
    for (int i = threadIdx.x; i < DM; i += 256) { float v = xr[i]; s += v*v; }
    __shared__ float red[256];
    red[threadIdx.x] = s; __syncthreads();
    for (int st = 128; st > 0; st >>= 1) {
        if (threadIdx.x < st) red[threadIdx.x] += red[threadIdx.x + st];
        __syncthreads();
    }
    float inv = rsqrtf(red[0] / (float)DM + 1e-5f);
    float* orow = o + (size_t)t*DM;
    for (int i = threadIdx.x; i < DM; i += 256) orow[i] = tf32r(xr[i]*inv*w[i]);
}

// ---------------- depthwise causal conv1d + SiLU ----------------
__global__ void conv_k(const float* __restrict__ zx, const float* __restrict__ cw,
                       const float* __restrict__ cb, float* __restrict__ xbc)
{
    int c = blockIdx.x*256 + threadIdx.x;   // < 6144
    int t = blockIdx.y;
    int l = t & (LSEQ - 1);
    const float* base = zx + (size_t)t*PROJ + 4096 + c;
    float w0 = cw[c*4+0], w1 = cw[c*4+1], w2 = cw[c*4+2], w3 = cw[c*4+3];
    float acc = cb[c] + w3*base[0];
    if (l >= 1) acc += w2*base[-(ptrdiff_t)PROJ];
    if (l >= 2) acc += w1*base[-(ptrdiff_t)(2*PROJ)];
    if (l >= 3) acc += w0*base[-(ptrdiff_t)(3*PROJ)];
    float sv = acc / (1.f + expf(-acc));
    xbc[(size_t)t*CONVD + c] = sv;
}

// ---------------- dt = softplus(dt_raw + bias), a = dt * (-exp(A_log)) ----------------
__global__ void dt_k(const float* __restrict__ zx, const float* __restrict__ dtb,
                     const float* __restrict__ Alog, float* __restrict__ dto,
                     float* __restrict__ ao)
{
    int idx = blockIdx.x*256 + threadIdx.x;
    if (idx >= TKN*NH) return;
    int t = idx >> 5, h = idx & 31;
    float raw = zx[(size_t)t*PROJ + 10240 + h] + dtb[h];
    float dt = (raw > 20.f) ? raw : log1pf(expf(raw));
    dto[idx] = dt;
    ao[idx]  = -expf(Alog[h]) * dt;
}

// ---------------- SSD stage 1: per (b,chunk,head) ----------------
__global__ void __launch_bounds__(256)
ssd1_k(const float* __restrict__ xbc, const float* __restrict__ dtv,
       const float* __restrict__ av, const float* __restrict__ Dv,
       float* __restrict__ Y, float* __restrict__ cso,
       float* __restrict__ gmo, float* __restrict__ states)
{
    extern __shared__ float sm[];
    float* att = sm;                 // 128*129 = 16512
    float* t1  = att + 128*129;      // 4224
    float* t2  = t1 + 4224;          // 4224
    float* cs  = t2 + 4224;          // 128
    float* dts = cs + 128;           // 128
    __shared__ float wsum[4];

    int blk = blockIdx.x;
    int h = blk & 31, ch = (blk >> 5) & 15, b = blk >> 9;
    int t0 = b*LSEQ + ch*128;
    int g  = h >> 2;
    int tid = threadIdx.x;
    int tx = tid & 15, ty = tid >> 4;

    float v = 0.f;
    if (tid < 128) {
        dts[tid] = dtv[(size_t)(t0+tid)*NH + h];
        v = av[(size_t)(t0+tid)*NH + h];
        #pragma unroll
        for (int off = 1; off < 32; off <<= 1) {
            float n = __shfl_up_sync(0xffffffffu, v, off);
            if ((tid & 31) >= off) v += n;
        }
        if ((tid & 31) == 31) wsum[tid >> 5] = v;
    }
    __syncthreads();
    if (tid < 128) {
        float add = 0.f;
        for (int w = 0; w < (tid >> 5); w++) add += wsum[w];
        float c = v + add;
        cs[tid] = c;
        cso[blk*128 + tid] = c;
    }
    __syncthreads();
    if (tid == 0) gmo[blk] = expf(cs[127]);

    const float* Cbase = xbc + 2048 + h*128;
    const float* Bbase = xbc + 1024 + g*128;
    const float* Xbase = xbc + g*128;

    float acc[8][8];
    #pragma unroll
    for (int i = 0; i < 8; i++)
        #pragma unroll
        for (int j = 0; j < 8; j++) acc[i][j] = 0.f;
    for (int nt = 0; nt < 4; nt++) {
        #pragma unroll
        for (int i = 0; i < 16; i++) {
            int idx = tid + i*256;
            int q = idx >> 5, n = idx & 31;
            t1[q*33+n] = Cbase[(size_t)(t0+q)*CONVD + nt*32 + n];
            t2[q*33+n] = Bbase[(size_t)(t0+q)*CONVD + nt*32 + n];
        }
        __syncthreads();
        #pragma unroll
        for (int n = 0; n < 32; n++) {
            float cr[8], br[8];
            #pragma unroll
            for (int i = 0; i < 8; i++) cr[i] = t1[(ty*8+i)*33 + n];
            #pragma unroll
            for (int j = 0; j < 8; j++) br[j] = t2[(tx*8+j)*33 + n];
            #pragma unroll
            for (int i = 0; i < 8; i++)
                #pragma unroll
                for (int j = 0; j < 8; j++)
                    acc[i][j] = fmaf(cr[i], br[j], acc[i][j]);
        }
        __syncthreads();
    }
    #pragma unroll
    for (int i = 0; i < 8; i++) {
        int q = ty*8 + i;
        #pragma unroll
        for (int j = 0; j < 8; j++) {
            int k = tx*8 + j;
            float f = (q >= k) ? expf(cs[q] - cs[k]) * dts[k] : 0.f;
            att[q*129 + k] = acc[i][j] * f;
        }
    }
    __syncthreads();

    #pragma unroll
    for (int i = 0; i < 8; i++)
        #pragma unroll
        for (int j = 0; j < 8; j++) acc[i][j] = 0.f;
    for (int kt = 0; kt < 4; kt++) {
        #pragma unroll
        for (int i = 0; i < 16; i++) {
            int idx = tid + i*256;
            int k = idx >> 7, p = idx & 127;
            t1[k*129 + p] = Xbase[(size_t)(t0 + kt*32 + k)*CONVD + p];
        }
        __syncthreads();
        #pragma unroll
        for (int k = 0; k < 32; k++) {
            float ar[8], xr[8];
            #pragma unroll
            for (int i = 0; i < 8; i++) ar[i] = att[(ty*8+i)*129 + kt*32 + k];
            #pragma unroll
            for (int j = 0; j < 8; j++) xr[j] = t1[k*129 + tx*8 + j];
            #pragma unroll
            for (int i = 0; i < 8; i++)
                #pragma unroll
                for (int j = 0; j < 8; j++)
                    acc[i][j] = fmaf(ar[i], xr[j], acc[i][j]);
        }
        __syncthreads();
    }
    float Dh = Dv[h];
    #pragma unroll
    for (int i = 0; i < 8; i++) {
        int q = ty*8 + i; int trow = t0 + q;
        #pragma unroll
        for (int j = 0; j < 8; j++) {
            int p = tx*8 + j;
            float xv = Xbase[(size_t)trow*CONVD + p];
            Y[(size_t)trow*DIN + h*128 + p] = acc[i][j] + Dh*xv;
        }
    }
    __syncthreads();

    #pragma unroll
    for (int i = 0; i < 8; i++)
        #pragma unroll
        for (int j = 0; j < 8; j++) acc[i][j] = 0.f;
    float clast = cs[127];
    for (int qt = 0; qt < 4; qt++) {
        #pragma unroll
        for (int i = 0; i < 16; i++) {
            int idx = tid + i*256;
            int q = idx >> 7, p = idx & 127;
            int qq = qt*32 + q;
            float w = expf(clast - cs[qq]) * dts[qq];
            t1[q*129 + p] = w * Xbase[(size_t)(t0+qq)*CONVD + p];
            t2[q*129 + p] = Bbase[(size_t)(t0+qq)*CONVD + p];
        }
        __syncthreads();
        #pragma unroll
        for (int k = 0; k < 32; k++) {
            float xr[8], br[8];
            #pragma unroll
            for (int i = 0; i < 8; i++) xr[i] = t1[k*129 + ty*8 + i];
            #pragma unroll
            for (int j = 0; j < 8; j++) br[j] = t2[k*129 + tx*8 + j];
            #pragma unroll
            for (int i = 0; i < 8; i++)
                #pragma unroll
                for (int j = 0; j < 8; j++)
                    acc[i][j] = fmaf(xr[i], br[j], acc[i][j]);
        }
        __syncthreads();
    }
    size_t sbase = (size_t)blk*HP*HN;
    #pragma unroll
    for (int i = 0; i < 8; i++)
        #pragma unroll
        for (int j = 0; j < 8; j++)
            states[sbase + (size_t)(ty*8+i)*HN + tx*8 + j] = acc[i][j];
}

// ---------------- inter-chunk recurrence ----------------
__global__ void scan_k(const float* __restrict__ states, const float* __restrict__ gm,
                       float* __restrict__ prev)
{
    int bh = blockIdx.x;
    int b = bh >> 5, h = bh & 31;
    int e0 = threadIdx.x;
    float S[16];
    #pragma unroll
    for (int e = 0; e < 16; e++) S[e] = 0.f;
    for (int ch = 0; ch < NCH; ch++) {
        int blk = (b*NCH + ch)*NH + h;
        float gv = gm[blk];
        size_t base = (size_t)blk*HP*HN;
        #pragma unroll
        for (int e = 0; e < 16; e++) {
            int idx = e0 + e*1024;
            prev[base + idx] = S[e];
            S[e] = gv*S[e] + states[base + idx];
        }
    }
}

// ---------------- SSD stage 2 ----------------
__global__ void __launch_bounds__(256)
ssd2_k(const float* __restrict__ xbc, const float* __restrict__ prev,
       const float* __restrict__ csv, float* __restrict__ Y)
{
    __shared__ float t1[128*33];
    __shared__ float t2[128*33];
    __shared__ float cs[128];
    int blk = blockIdx.x;
    int h = blk & 31, ch = (blk >> 5) & 15, b = blk >> 9;
    int t0 = b*LSEQ + ch*128;
    int tid = threadIdx.x, tx = tid & 15, ty = tid >> 4;
    if (tid < 128) cs[tid] = csv[blk*128 + tid];
    float acc[8][8];
    #pragma unroll
    for (int i = 0; i < 8; i++)
        #pragma unroll
        for (int j = 0; j < 8; j++) acc[i][j] = 0.f;
    const float* Cbase = xbc + 2048 + h*128;
    size_t pbase = (size_t)blk*HP*HN;
    for (int nt = 0; nt < 4; nt++) {
        #pragma unroll
        for (int i = 0; i < 16; i++) {
            int idx = tid + i*256;
            int r = idx >> 5, n = idx & 31;
            t1[r*33+n] = Cbase[(size_t)(t0+r)*CONVD + nt*32 + n];
            t2[r*33+n] = prev[pbase + (size_t)r*HN + nt*32 + n];
        }
        __syncthreads();
        #pragma unroll
        for (int n = 0; n < 32; n++) {
            float cr[8], pr[8];
            #pragma unroll
            for (int i = 0; i < 8; i++) cr[i] = t1[(ty*8+i)*33 + n];
            #pragma unroll
            for (int j = 0; j < 8; j++) pr[j] = t2[(tx*8+j)*33 + n];
            #pragma unroll
            for (int i = 0; i < 8; i++)
                #pragma unroll
                for (int j = 0; j < 8; j++)
                    acc[i][j] = fmaf(cr[i], pr[j], acc[i][j]);
        }
        __syncthreads();
    }
    #pragma unroll
    for (int i = 0; i < 8; i++) {
        int q = ty*8 + i;
        float eq = expf(cs[q]);
        #pragma unroll
        for (int j = 0; j < 8; j++) {
            int p = tx*8 + j;
            size_t off = (size_t)(t0+q)*DIN + h*128 + p;
            Y[off] += eq * acc[i][j];
        }
    }
}

// ---------------- y = Y * silu(z)  (tf32-rounded: A of out_proj) ----------------
__global__ void gate_y_k(const float* __restrict__ zx, float* __restrict__ Y)
{
    int idx = blockIdx.x*256 + threadIdx.x;
    int t = idx >> 12, d = idx & 4095;
    float z = zx[(size_t)t*PROJ + d];
    float s = z / (1.f + expf(-z));
    Y[idx] = tf32r(Y[idx] * s);
}

// ---------------- act = silu(gate) * up  (tf32-rounded: A of down_proj) ----------------
__global__ void act_k(float* __restrict__ ga, const float* __restrict__ up)
{
    size_t idx = (size_t)blockIdx.x*256 + threadIdx.x;
    float gv = ga[idx];
    ga[idx] = tf32r((gv / (1.f + expf(-gv))) * up[idx]);
}

// ---------------- launcher ----------------
extern "C" void kernel_launch(void* const* d_in, const int* in_sizes, int n_in,
                              void* d_out, int out_size)
{
    const float* hidden = (const float*)d_in[0];
    const float* w_in   = (const float*)d_in[1];
    const float* conv_w = (const float*)d_in[2];
    const float* conv_b = (const float*)d_in[3];
    const float* A_log  = (const float*)d_in[4];
    const float* Dv     = (const float*)d_in[5];
    const float* dt_b   = (const float*)d_in[6];
    const float* w_out  = (const float*)d_in[7];
    const float* ln1    = (const float*)d_in[8];
    const float* ln2    = (const float*)d_in[9];
    const float* gate_w = (const float*)d_in[10];
    const float* up_w   = (const float*)d_in[11];
    const float* down_w = (const float*)d_in[12];
    float* out = (float*)d_out;

    float *hnorm, *zx, *xbc, *dt, *av, *cs, *gm, *st, *pv, *Y, *h, *h2, *ga, *up;
    cudaGetSymbolAddress((void**)&hnorm, d_hnorm);
    cudaGetSymbolAddress((void**)&zx,    d_zx);
    cudaGetSymbolAddress((void**)&xbc,   d_xbc);
    cudaGetSymbolAddress((void**)&dt,    d_dt);
    cudaGetSymbolAddress((void**)&av,    d_av);
    cudaGetSymbolAddress((void**)&cs,    d_cs);
    cudaGetSymbolAddress((void**)&gm,    d_gm);
    cudaGetSymbolAddress((void**)&st,    d_states);
    cudaGetSymbolAddress((void**)&pv,    d_prev);
    cudaGetSymbolAddress((void**)&Y,     d_Y);
    cudaGetSymbolAddress((void**)&h,     d_h);
    cudaGetSymbolAddress((void**)&h2,    d_h2);
    cudaGetSymbolAddress((void**)&ga,    d_ga);
    cudaGetSymbolAddress((void**)&up,    d_up);

    cudaFuncSetAttribute(gemm_mma, cudaFuncAttributeMaxDynamicSharedMemorySize, GSMEM_DYN);

    // 1) pre-norm (tf32-rounded output)
    rmsnorm_k<<<TKN, 256>>>(hidden, ln1, hnorm);
    // 2) in_proj
    gemm_mma<<<gemm_grid(PROJ), 256, GSMEM_DYN>>>(hnorm, w_in, nullptr, zx, PROJ, DM);
    // 3) depthwise causal conv + SiLU
    conv_k<<<dim3(24, TKN), 256>>>(zx, conv_w, conv_b, xbc);
    // 4) dt / a
    dt_k<<<(TKN*NH)/256, 256>>>(zx, dt_b, A_log, dt, av);
    // 5) SSD stage 1
    int smem1 = (128*129 + 4224 + 4224 + 128 + 128) * 4;
    cudaFuncSetAttribute(ssd1_k, cudaFuncAttributeMaxDynamicSharedMemorySize, smem1);
    ssd1_k<<<NBLK, 256, smem1>>>(xbc, dt, av, Dv, Y, cs, gm, st);
    // 6) inter-chunk recurrence
    scan_k<<<NB*NH, 1024>>>(st, gm, pv);
    // 7) SSD stage 2
    ssd2_k<<<NBLK, 256>>>(xbc, pv, cs, Y);
    // 8) gate with silu(z)
    gate_y_k<<<(TKN*DIN)/256, 256>>>(zx, Y);
    // 9) out_proj + residual
    gemm_mma<<<gemm_grid(DM), 256, GSMEM_DYN>>>(Y, w_out, hidden, h, DM, DIN);
    // 10) second norm (tf32-rounded output)
    rmsnorm_k<<<TKN, 256>>>(h, ln2, h2);
    // 11) MLP
    gemm_mma<<<gemm_grid(INTERD), 256, GSMEM_DYN>>>(h2, gate_w, nullptr, ga, INTERD, DM);
    gemm_mma<<<gemm_grid(INTERD), 256, GSMEM_DYN>>>(h2, up_w,   nullptr, up, INTERD, DM);
    act_k<<<((size_t)TKN*INTERD)/256, 256>>>(ga, up);
    // 12) down_proj + residual -> out
    gemm_mma<<<gemm_grid(DM), 256, GSMEM_DYN>>>(ga, down_w, h, out, DM, INTERD);
}

// round 6
// speedup vs baseline: 1.1014x; 1.1014x over previous
#include <cuda_runtime.h>
#include <math.h>
#include <stdint.h>

// ---------------- fixed shapes ----------------
#define TKN   4096          // B*L tokens
#define NB    2
#define LSEQ  2048
#define DM    4096          // d_model
#define DXB   1024
#define DIN   4096          // d_inner
#define NH    32            // heads
#define HP    128           // headdim P
#define HN    128           // dstate N
#define PROJ  10272         // 2*DIN + 2*DXB + NH
#define CONVD 6144          // 2*DXB + DIN
#define INTERD 14336
#define NCH   16            // chunks per batch (2048/128)
#define NBLK  (NB*NCH*NH)   // 1024 ssd blocks

// ---------------- scratch (static device globals; no allocations) ----------------
__device__ float d_hnorm[TKN*DM];
__device__ float d_zx[TKN*PROJ];
__device__ float d_xbc[TKN*CONVD];
__device__ float d_dt[TKN*NH];
__device__ float d_av[TKN*NH];
__device__ float d_cs[NBLK*128];
__device__ float d_gm[NBLK];
__device__ float d_states[(size_t)NBLK*HP*HN];
__device__ float d_prev[(size_t)NBLK*HP*HN];
__device__ float d_Y[TKN*DIN];
__device__ float d_h[TKN*DM];
__device__ float d_h2[TKN*DM];
__device__ float d_ga[(size_t)TKN*INTERD];
__device__ float d_up[(size_t)TKN*INTERD];
// tf32-pre-rounded weights
__device__ float d_win_r[(size_t)PROJ*DM];
__device__ float d_wout_r[(size_t)DM*DIN];
__device__ float d_gate_r[(size_t)INTERD*DM];
__device__ float d_upw_r[(size_t)INTERD*DM];
__device__ float d_down_r[(size_t)DM*INTERD];

// tf32 round-to-nearest helpers
static __device__ __forceinline__ float tf32r(float x) {
    uint32_t u; asm("cvt.rna.tf32.f32 %0, %1;" : "=r"(u) : "f"(x));
    return __uint_as_float(u);
}

// ---------------- pre-round weights to tf32 (float4 grid-stride) ----------------
__global__ void round_tf32_k(const float* __restrict__ src, float* __restrict__ dst, int n4)
{
    int stride = gridDim.x * blockDim.x;
    for (int i = blockIdx.x*blockDim.x + threadIdx.x; i < n4; i += stride) {
        float4 v = reinterpret_cast<const float4*>(src)[i];
        v.x = tf32r(v.x); v.y = tf32r(v.y); v.z = tf32r(v.z); v.w = tf32r(v.w);
        reinterpret_cast<float4*>(dst)[i] = v;
    }
}

// ================= tf32 mma.sync GEMM =================
// C[M,N] = A[M,K] @ B[N,K]^T. M=4096, K mult of 32, N even (guarded).
// A and B are both tf32-pre-rounded. CTA tile 128x128, BK=32, 3-stage cp.async
// pipeline, 8 warps (2m x 4n), warp tile 64x32, 2 CTAs/SM.
// Grouped rasterization (GROUP_M=8). mode: 0 plain, 1 +=Res, 2 C=tf32r(silu(Res)*acc).

#define GSTAGE 32768
#define GSMEM_DYN (3*GSTAGE)
#define GROUP_M 8

__global__ void __launch_bounds__(256, 2)
gemm_mma(const float* __restrict__ A, const float* __restrict__ Bw,
         const float* __restrict__ Res, float* __restrict__ C,
         int N, int K, int mode)
{
    extern __shared__ char smraw[];
    const int tid  = threadIdx.x;
    const int lane = tid & 31, warp = tid >> 5;
    const int wm = warp & 1, wn = warp >> 1;        // 2 x 4 warp grid
    const int T = K >> 5;
    uint32_t sbase = (uint32_t)__cvta_generic_to_shared(smraw);

    // grouped rasterization (num_pid_m = 32, divisible by GROUP_M)
    const int num_pid_n = (N + 127) >> 7;
    int pid = blockIdx.x;
    int npg = GROUP_M * num_pid_n;
    int pid_m = (pid / npg) * GROUP_M + (pid % GROUP_M);
    int pid_n = (pid % npg) / GROUP_M;
    const int bm = pid_m << 7, bn = pid_n << 7;

    // stage: A 16KB (128 rows x 128B) + B 16KB, 16B-chunk swizzled
    auto load_tile = [&](int t) {
        uint32_t s = sbase + (uint32_t)(t % 3) * GSTAGE;
        int k0 = t << 5;
        #pragma unroll
        for (int i = 0; i < 4; i++) {
            int idx = i*256 + tid, row = idx >> 3, c = idx & 7;
            uint32_t dst = s + row*128 + (uint32_t)((c ^ (row & 7)) << 4);
            asm volatile("cp.async.cg.shared.global [%0], [%1], 16;"
                         :: "r"(dst), "l"(A + (size_t)(bm + row)*K + k0 + c*4));
        }
        #pragma unroll
        for (int i = 0; i < 4; i++) {
            int idx = i*256 + tid, row = idx >> 3, c = idx & 7;
            int brow = bn + row; if (brow >= N) brow = N - 1;
            uint32_t dst = s + 16384u + row*128 + (uint32_t)((c ^ (row & 7)) << 4);
            asm volatile("cp.async.cg.shared.global [%0], [%1], 16;"
                         :: "r"(dst), "l"(Bw + (size_t)brow*K + k0 + c*4));
        }
    };

    float acc[4][4][4];
    #pragma unroll
    for (int a = 0; a < 4; a++)
        #pragma unroll
        for (int b = 0; b < 4; b++)
            #pragma unroll
            for (int c = 0; c < 4; c++) acc[a][b][c] = 0.f;

    load_tile(0);
    asm volatile("cp.async.commit_group;" ::: "memory");
    load_tile(1);
    asm volatile("cp.async.commit_group;" ::: "memory");

    for (int t = 0; t < T; t++) {
        if (t + 2 < T) load_tile(t + 2);
        asm volatile("cp.async.commit_group;" ::: "memory");
        asm volatile("cp.async.wait_group 2;" ::: "memory");
        __syncthreads();

        uint32_t as = sbase + (uint32_t)(t % 3) * GSTAGE;
        uint32_t bs = as + 16384u;

        #pragma unroll
        for (int kk = 0; kk < 4; kk++) {
            // A fragments: 4 m-tiles via ldmatrix.x4
            uint32_t af[4][4];
            #pragma unroll
            for (int mt = 0; mt < 4; mt++) {
                int m  = wm*64 + mt*16 + (lane & 7) + ((lane >> 3) & 1) * 8;
                int kc = kk*2 + (lane >> 4);
                uint32_t addr = as + m*128 + (uint32_t)((kc ^ (m & 7)) << 4);
                asm volatile("ldmatrix.sync.aligned.m8n8.x4.shared.b16 {%0,%1,%2,%3}, [%4];"
                             : "=r"(af[mt][0]), "=r"(af[mt][1]),
                               "=r"(af[mt][2]), "=r"(af[mt][3]) : "r"(addr));
            }
            #pragma unroll
            for (int nt = 0; nt < 4; nt++) {
                // B pair via one ldmatrix.x2 (pre-rounded: no cvt needed)
                int nrow = wn*32 + nt*8 + (lane & 7);
                int bc = kk*2 + ((lane >> 3) & 1);
                uint32_t baddr = bs + nrow*128 + (uint32_t)((bc ^ (nrow & 7)) << 4);
                uint32_t b0, b1;
                asm volatile("ldmatrix.sync.aligned.m8n8.x2.shared.b16 {%0,%1}, [%2];"
                             : "=r"(b0), "=r"(b1) : "r"(baddr));
                #pragma unroll
                for (int mt = 0; mt < 4; mt++) {
                    asm volatile(
                        "mma.sync.aligned.m16n8k8.row.col.f32.tf32.tf32.f32 "
                        "{%0,%1,%2,%3}, {%4,%5,%6,%7}, {%8,%9}, {%0,%1,%2,%3};"
                        : "+f"(acc[mt][nt][0]), "+f"(acc[mt][nt][1]),
                          "+f"(acc[mt][nt][2]), "+f"(acc[mt][nt][3])
                        : "r"(af[mt][0]), "r"(af[mt][1]), "r"(af[mt][2]), "r"(af[mt][3]),
                          "r"(b0), "r"(b1));
                }
            }
        }
        __syncthreads();
    }

    // epilogue
    #pragma unroll
    for (int mt = 0; mt < 4; mt++) {
        int r0 = bm + wm*64 + mt*16 + (lane >> 2);
        #pragma unroll
        for (int nt = 0; nt < 4; nt++) {
            int c0 = bn + wn*32 + nt*8 + 2*(lane & 3);
            if (c0 < N) {
                float2 v0 = make_float2(acc[mt][nt][0], acc[mt][nt][1]);
                float2 v1 = make_float2(acc[mt][nt][2], acc[mt][nt][3]);
                if (mode == 1) {
                    float2 q0 = *reinterpret_cast<const float2*>(Res + (size_t)r0*N + c0);
                    float2 q1 = *reinterpret_cast<const float2*>(Res + (size_t)(r0+8)*N + c0);
                    v0.x += q0.x; v0.y += q0.y; v1.x += q1.x; v1.y += q1.y;
                } else if (mode == 2) {
                    float2 g0 = *reinterpret_cast<const float2*>(Res + (size_t)r0*N + c0);
                    float2 g1 = *reinterpret_cast<const float2*>(Res + (size_t)(r0+8)*N + c0);
                    v0.x = tf32r(v0.x * (g0.x / (1.f + expf(-g0.x))));
                    v0.y = tf32r(v0.y * (g0.y / (1.f + expf(-g0.y))));
                    v1.x = tf32r(v1.x * (g1.x / (1.f + expf(-g1.x))));
                    v1.y = tf32r(v1.y * (g1.y / (1.f + expf(-g1.y))));
                }
                *reinterpret_cast<float2*>(C + (size_t)r0*N + c0)     = v0;
                *reinterpret_cast<float2*>(C + (size_t)(r0+8)*N + c0) = v1;
            }
        }
    }
}

static inline int gemm_grid(int N) { return 32 * ((N + 127) >> 7); }

// ---------------- RMSNorm (output tf32-rounded: feeds GEMM A operands) ----------------
__global__ void rmsnorm_k(const float* __restrict__ x, const float* __restrict__ w,
                          float* __restrict__ o)
{
    int t = blockIdx.x;
    const float* xr = x + (size_t)t*DM;
    float s = 0.f;
    for (int i = threadIdx.x; i < DM; i += 256) { float v = xr[i]; s += v*v; }
    __shared__ float red[256];
    red[threadIdx.x] = s; __syncthreads();
    for (int st = 128; st > 0; st >>= 1) {
        if (threadIdx.x < st) red[threadIdx.x] += red[threadIdx.x + st];
        __syncthreads();
    }
    float inv = rsqrtf(red[0] / (float)DM + 1e-5f);
    float* orow = o + (size_t)t*DM;
    for (int i = threadIdx.x; i < DM; i += 256) orow[i] = tf32r(xr[i]*inv*w[i]);
}

// ---------------- depthwise causal conv1d + SiLU ----------------
__global__ void conv_k(const float* __restrict__ zx, const float* __restrict__ cw,
                       const float* __restrict__ cb, float* __restrict__ xbc)
{
    int c = blockIdx.x*256 + threadIdx.x;   // < 6144
    int t = blockIdx.y;
    int l = t & (LSEQ - 1);
    const float* base = zx + (size_t)t*PROJ + 4096 + c;
    float w0 = cw[c*4+0], w1 = cw[c*4+1], w2 = cw[c*4+2], w3 = cw[c*4+3];
    float acc = cb[c] + w3*base[0];
    if (l >= 1) acc += w2*base[-(ptrdiff_t)PROJ];
    if (l >= 2) acc += w1*base[-(ptrdiff_t)(2*PROJ)];
    if (l >= 3) acc += w0*base[-(ptrdiff_t)(3*PROJ)];
    float sv = acc / (1.f + expf(-acc));
    xbc[(size_t)t*CONVD + c] = sv;
}

// ---------------- dt = softplus(dt_raw + bias), a = dt * (-exp(A_log)) ----------------
__global__ void dt_k(const float* __restrict__ zx, const float* __restrict__ dtb,
                     const float* __restrict__ Alog, float* __restrict__ dto,
                     float* __restrict__ ao)
{
    int idx = blockIdx.x*256 + threadIdx.x;
    if (idx >= TKN*NH) return;
    int t = idx >> 5, h = idx & 31;
    float raw = zx[(size_t)t*PROJ + 10240 + h] + dtb[h];
    float dt = (raw > 20.f) ? raw : log1pf(expf(raw));
    dto[idx] = dt;
    ao[idx]  = -expf(Alog[h]) * dt;
}

// ---------------- SSD stage 1: per (b,chunk,head) ----------------
__global__ void __launch_bounds__(256)
ssd1_k(const float* __restrict__ xbc, const float* __restrict__ dtv,
       const float* __restrict__ av, const float* __restrict__ Dv,
       float* __restrict__ Y, float* __restrict__ cso,
       float* __restrict__ gmo, float* __restrict__ states)
{
    extern __shared__ float sm[];
    float* att = sm;                 // 128*129 = 16512
    float* t1  = att + 128*129;      // 4224
    float* t2  = t1 + 4224;          // 4224
    float* cs  = t2 + 4224;          // 128
    float* dts = cs + 128;           // 128
    __shared__ float wsum[4];

    int blk = blockIdx.x;
    int h = blk & 31, ch = (blk >> 5) & 15, b = blk >> 9;
    int t0 = b*LSEQ + ch*128;
    int g  = h >> 2;
    int tid = threadIdx.x;
    int tx = tid & 15, ty = tid >> 4;

    float v = 0.f;
    if (tid < 128) {
        dts[tid] = dtv[(size_t)(t0+tid)*NH + h];
        v = av[(size_t)(t0+tid)*NH + h];
        #pragma unroll
        for (int off = 1; off < 32; off <<= 1) {
            float n = __shfl_up_sync(0xffffffffu, v, off);
            if ((tid & 31) >= off) v += n;
        }
        if ((tid & 31) == 31) wsum[tid >> 5] = v;
    }
    __syncthreads();
    if (tid < 128) {
        float add = 0.f;
        for (int w = 0; w < (tid >> 5); w++) add += wsum[w];
        float c = v + add;
        cs[tid] = c;
        cso[blk*128 + tid] = c;
    }
    __syncthreads();
    if (tid == 0) gmo[blk] = expf(cs[127]);

    const float* Cbase = xbc + 2048 + h*128;
    const float* Bbase = xbc + 1024 + g*128;
    const float* Xbase = xbc + g*128;

    float acc[8][8];
    #pragma unroll
    for (int i = 0; i < 8; i++)
        #pragma unroll
        for (int j = 0; j < 8; j++) acc[i][j] = 0.f;
    for (int nt = 0; nt < 4; nt++) {
        #pragma unroll
        for (int i = 0; i < 16; i++) {
            int idx = tid + i*256;
            int q = idx >> 5, n = idx & 31;
            t1[q*33+n] = Cbase[(size_t)(t0+q)*CONVD + nt*32 + n];
            t2[q*33+n] = Bbase[(size_t)(t0+q)*CONVD + nt*32 + n];
        }
        __syncthreads();
        #pragma unroll
        for (int n = 0; n < 32; n++) {
            float cr[8], br[8];
            #pragma unroll
            for (int i = 0; i < 8; i++) cr[i] = t1[(ty*8+i)*33 + n];
            #pragma unroll
            for (int j = 0; j < 8; j++) br[j] = t2[(tx*8+j)*33 + n];
            #pragma unroll
            for (int i = 0; i < 8; i++)
                #pragma unroll
                for (int j = 0; j < 8; j++)
                    acc[i][j] = fmaf(cr[i], br[j], acc[i][j]);
        }
        __syncthreads();
    }
    #pragma unroll
    for (int i = 0; i < 8; i++) {
        int q = ty*8 + i;
        #pragma unroll
        for (int j = 0; j < 8; j++) {
            int k = tx*8 + j;
            float f = (q >= k) ? expf(cs[q] - cs[k]) * dts[k] : 0.f;
            att[q*129 + k] = acc[i][j] * f;
        }
    }
    __syncthreads();

    #pragma unroll
    for (int i = 0; i < 8; i++)
        #pragma unroll
        for (int j = 0; j < 8; j++) acc[i][j] = 0.f;
    for (int kt = 0; kt < 4; kt++) {
        #pragma unroll
        for (int i = 0; i < 16; i++) {
            int idx = tid + i*256;
            int k = idx >> 7, p = idx & 127;
            t1[k*129 + p] = Xbase[(size_t)(t0 + kt*32 + k)*CONVD + p];
        }
        __syncthreads();
        #pragma unroll
        for (int k = 0; k < 32; k++) {
            float ar[8], xr[8];
            #pragma unroll
            for (int i = 0; i < 8; i++) ar[i] = att[(ty*8+i)*129 + kt*32 + k];
            #pragma unroll
            for (int j = 0; j < 8; j++) xr[j] = t1[k*129 + tx*8 + j];
            #pragma unroll
            for (int i = 0; i < 8; i++)
                #pragma unroll
                for (int j = 0; j < 8; j++)
                    acc[i][j] = fmaf(ar[i], xr[j], acc[i][j]);
        }
        __syncthreads();
    }
    float Dh = Dv[h];
    #pragma unroll
    for (int i = 0; i < 8; i++) {
        int q = ty*8 + i; int trow = t0 + q;
        #pragma unroll
        for (int j = 0; j < 8; j++) {
            int p = tx*8 + j;
            float xv = Xbase[(size_t)trow*CONVD + p];
            Y[(size_t)trow*DIN + h*128 + p] = acc[i][j] + Dh*xv;
        }
    }
    __syncthreads();

    #pragma unroll
    for (int i = 0; i < 8; i++)
        #pragma unroll
        for (int j = 0; j < 8; j++) acc[i][j] = 0.f;
    float clast = cs[127];
    for (int qt = 0; qt < 4; qt++) {
        #pragma unroll
        for (int i = 0; i < 16; i++) {
            int idx = tid + i*256;
            int q = idx >> 7, p = idx & 127;
            int qq = qt*32 + q;
            float w = expf(clast - cs[qq]) * dts[qq];
            t1[q*129 + p] = w * Xbase[(size_t)(t0+qq)*CONVD + p];
            t2[q*129 + p] = Bbase[(size_t)(t0+qq)*CONVD + p];
        }
        __syncthreads();
        #pragma unroll
        for (int k = 0; k < 32; k++) {
            float xr[8], br[8];
            #pragma unroll
            for (int i = 0; i < 8; i++) xr[i] = t1[k*129 + ty*8 + i];
            #pragma unroll
            for (int j = 0; j < 8; j++) br[j] = t2[k*129 + tx*8 + j];
            #pragma unroll
            for (int i = 0; i < 8; i++)
                #pragma unroll
                for (int j = 0; j < 8; j++)
                    acc[i][j] = fmaf(xr[i], br[j], acc[i][j]);
        }
        __syncthreads();
    }
    size_t sbase = (size_t)blk*HP*HN;
    #pragma unroll
    for (int i = 0; i < 8; i++)
        #pragma unroll
        for (int j = 0; j < 8; j++)
            states[sbase + (size_t)(ty*8+i)*HN + tx*8 + j] = acc[i][j];
}

// ---------------- inter-chunk recurrence ----------------
__global__ void scan_k(const float* __restrict__ states, const float* __restrict__ gm,
                       float* __restrict__ prev)
{
    int bh = blockIdx.x;
    int b = bh >> 5, h = bh & 31;
    int e0 = threadIdx.x;
    float S[16];
    #pragma unroll
    for (int e = 0; e < 16; e++) S[e] = 0.f;
    for (int ch = 0; ch < NCH; ch++) {
        int blk = (b*NCH + ch)*NH + h;
        float gv = gm[blk];
        size_t base = (size_t)blk*HP*HN;
        #pragma unroll
        for (int e = 0; e < 16; e++) {
            int idx = e0 + e*1024;
            prev[base + idx] = S[e];
            S[e] = gv*S[e] + states[base + idx];
        }
    }
}

// ---------------- SSD stage 2 (+ fused silu(z) gating, tf32-rounded output) ----------------
__global__ void __launch_bounds__(256)
ssd2_k(const float* __restrict__ xbc, const float* __restrict__ prev,
       const float* __restrict__ csv, const float* __restrict__ zx,
       float* __restrict__ Y)
{
    __shared__ float t1[128*33];
    __shared__ float t2[128*33];
    __shared__ float cs[128];
    int blk = blockIdx.x;
    int h = blk & 31, ch = (blk >> 5) & 15, b = blk >> 9;
    int t0 = b*LSEQ + ch*128;
    int tid = threadIdx.x, tx = tid & 15, ty = tid >> 4;
    if (tid < 128) cs[tid] = csv[blk*128 + tid];
    float acc[8][8];
    #pragma unroll
    for (int i = 0; i < 8; i++)
        #pragma unroll
        for (int j = 0; j < 8; j++) acc[i][j] = 0.f;
    const float* Cbase = xbc + 2048 + h*128;
    size_t pbase = (size_t)blk*HP*HN;
    for (int nt = 0; nt < 4; nt++) {
        #pragma unroll
        for (int i = 0; i < 16; i++) {
            int idx = tid + i*256;
            int r = idx >> 5, n = idx & 31;
            t1[r*33+n] = Cbase[(size_t)(t0+r)*CONVD + nt*32 + n];
            t2[r*33+n] = prev[pbase + (size_t)r*HN + nt*32 + n];
        }
        __syncthreads();
        #pragma unroll
        for (int n = 0; n < 32; n++) {
            float cr[8], pr[8];
            #pragma unroll
            for (int i = 0; i < 8; i++) cr[i] = t1[(ty*8+i)*33 + n];
            #pragma unroll
            for (int j = 0; j < 8; j++) pr[j] = t2[(tx*8+j)*33 + n];
            #pragma unroll
            for (int i = 0; i < 8; i++)
                #pragma unroll
                for (int j = 0; j < 8; j++)
                    acc[i][j] = fmaf(cr[i], pr[j], acc[i][j]);
        }
        __syncthreads();
    }
    #pragma unroll
    for (int i = 0; i < 8; i++) {
        int q = ty*8 + i;
        float eq = expf(cs[q]);
        #pragma unroll
        for (int j = 0; j < 8; j++) {
            int p = tx*8 + j;
            size_t off = (size_t)(t0+q)*DIN + h*128 + p;
            float z = zx[(size_t)(t0+q)*PROJ + h*128 + p];
            float s = z / (1.f + expf(-z));
            Y[off] = tf32r((Y[off] + eq * acc[i][j]) * s);
        }
    }
}

// ---------------- launcher ----------------
extern "C" void kernel_launch(void* const* d_in, const int* in_sizes, int n_in,
                              void* d_out, int out_size)
{
    const float* hidden = (const float*)d_in[0];
    const float* w_in   = (const float*)d_in[1];
    const float* conv_w = (const float*)d_in[2];
    const float* conv_b = (const float*)d_in[3];
    const float* A_log  = (const float*)d_in[4];
    const float* Dv     = (const float*)d_in[5];
    const float* dt_b   = (const float*)d_in[6];
    const float* w_out  = (const float*)d_in[7];
    const float* ln1    = (const float*)d_in[8];
    const float* ln2    = (const float*)d_in[9];
    const float* gate_w = (const float*)d_in[10];
    const float* up_w   = (const float*)d_in[11];
    const float* down_w = (const float*)d_in[12];
    float* out = (float*)d_out;

    float *hnorm, *zx, *xbc, *dt, *av, *cs, *gm, *st, *pv, *Y, *h, *h2, *ga, *up;
    float *winr, *woutr, *gater, *upr, *downr;
    cudaGetSymbolAddress((void**)&hnorm, d_hnorm);
    cudaGetSymbolAddress((void**)&zx,    d_zx);
    cudaGetSymbolAddress((void**)&xbc,   d_xbc);
    cudaGetSymbolAddress((void**)&dt,    d_dt);
    cudaGetSymbolAddress((void**)&av,    d_av);
    cudaGetSymbolAddress((void**)&cs,    d_cs);
    cudaGetSymbolAddress((void**)&gm,    d_gm);
    cudaGetSymbolAddress((void**)&st,    d_states);
    cudaGetSymbolAddress((void**)&pv,    d_prev);
    cudaGetSymbolAddress((void**)&Y,     d_Y);
    cudaGetSymbolAddress((void**)&h,     d_h);
    cudaGetSymbolAddress((void**)&h2,    d_h2);
    cudaGetSymbolAddress((void**)&ga,    d_ga);
    cudaGetSymbolAddress((void**)&up,    d_up);
    cudaGetSymbolAddress((void**)&winr,  d_win_r);
    cudaGetSymbolAddress((void**)&woutr, d_wout_r);
    cudaGetSymbolAddress((void**)&gater, d_gate_r);
    cudaGetSymbolAddress((void**)&upr,   d_upw_r);
    cudaGetSymbolAddress((void**)&downr, d_down_r);

    cudaFuncSetAttribute(gemm_mma, cudaFuncAttributeMaxDynamicSharedMemorySize, GSMEM_DYN);

    // 0) pre-round weights to tf32 (removes cvt from GEMM hot loops)
    round_tf32_k<<<1024, 256>>>(w_in,   winr,  (PROJ*DM)/4);
    round_tf32_k<<<1024, 256>>>(w_out,  woutr, (DM*DIN)/4);
    round_tf32_k<<<1024, 256>>>(gate_w, gater, (INTERD*DM)/4);
    round_tf32_k<<<1024, 256>>>(up_w,   upr,   (INTERD*DM)/4);
    round_tf32_k<<<1024, 256>>>(down_w, downr, (DM*INTERD)/4);

    // 1) pre-norm (tf32-rounded output)
    rmsnorm_k<<<TKN, 256>>>(hidden, ln1, hnorm);
    // 2) in_proj
    gemm_mma<<<gemm_grid(PROJ), 256, GSMEM_DYN>>>(hnorm, winr, nullptr, zx, PROJ, DM, 0);
    // 3) depthwise causal conv + SiLU
    conv_k<<<dim3(24, TKN), 256>>>(zx, conv_w, conv_b, xbc);
    // 4) dt / a
    dt_k<<<(TKN*NH)/256, 256>>>(zx, dt_b, A_log, dt, av);
    // 5) SSD stage 1
    int smem1 = (128*129 + 4224 + 4224 + 128 + 128) * 4;
    cudaFuncSetAttribute(ssd1_k, cudaFuncAttributeMaxDynamicSharedMemorySize, smem1);
    ssd1_k<<<NBLK, 256, smem1>>>(xbc, dt, av, Dv, Y, cs, gm, st);
    // 6) inter-chunk recurrence
    scan_k<<<NB*NH, 1024>>>(st, gm, pv);
    // 7) SSD stage 2 + fused silu(z) gating
    ssd2_k<<<NBLK, 256>>>(xbc, pv, cs, zx, Y);
    // 8) out_proj + residual
    gemm_mma<<<gemm_grid(DM), 256, GSMEM_DYN>>>(Y, woutr, hidden, h, DM, DIN, 1);
    // 9) second norm (tf32-rounded output)
    rmsnorm_k<<<TKN, 256>>>(h, ln2, h2);
    // 10) MLP: gate GEMM, then up GEMM with fused silu(gate)*up
    gemm_mma<<<gemm_grid(INTERD), 256, GSMEM_DYN>>>(h2, gater, nullptr, ga, INTERD, DM, 0);
    gemm_mma<<<gemm_grid(INTERD), 256, GSMEM_DYN>>>(h2, upr, ga, up, INTERD, DM, 2);
    // 11) down_proj + residual -> out
    gemm_mma<<<gemm_grid(DM), 256, GSMEM_DYN>>>(up, downr, h, out, DM, INTERD, 1);
}

// round 7
// speedup vs baseline: 1.1337x; 1.0293x over previous
#include <cuda_runtime.h>
#include <math.h>
#include <stdint.h>

// ---------------- fixed shapes ----------------
#define TKN   4096          // B*L tokens
#define NB    2
#define LSEQ  2048
#define DM    4096          // d_model
#define DXB   1024
#define DIN   4096          // d_inner
#define NH    32            // heads
#define HP    128           // headdim P
#define HN    128           // dstate N
#define PROJ  10272         // 2*DIN + 2*DXB + NH
#define CONVD 6144          // 2*DXB + DIN
#define INTERD 14336
#define NCH   16            // chunks per batch (2048/128)
#define NBLK  (NB*NCH*NH)   // 1024 ssd blocks

// ---------------- scratch (static device globals; no allocations) ----------------
__device__ float d_hnorm[TKN*DM];
__device__ float d_zx[TKN*PROJ];
__device__ float d_xbc[TKN*CONVD];
__device__ float d_dt[TKN*NH];
__device__ float d_av[TKN*NH];
__device__ float d_cs[NBLK*128];
__device__ float d_gm[NBLK];
__device__ float d_states[(size_t)NBLK*HP*HN];
__device__ float d_prev[(size_t)NBLK*HP*HN];
__device__ float d_Y[TKN*DIN];
__device__ float d_h[TKN*DM];
__device__ float d_h2[TKN*DM];
__device__ float d_ga[(size_t)TKN*INTERD];
__device__ float d_up[(size_t)TKN*INTERD];
// tf32-pre-rounded weights
__device__ float d_win_r[(size_t)PROJ*DM];
__device__ float d_wout_r[(size_t)DM*DIN];
__device__ float d_gate_r[(size_t)INTERD*DM];
__device__ float d_upw_r[(size_t)INTERD*DM];
__device__ float d_down_r[(size_t)DM*INTERD];

// tf32 round-to-nearest helpers
static __device__ __forceinline__ float tf32r(float x) {
    uint32_t u; asm("cvt.rna.tf32.f32 %0, %1;" : "=r"(u) : "f"(x));
    return __uint_as_float(u);
}

// ---------------- pre-round weights to tf32 (float4 grid-stride) ----------------
__global__ void round_tf32_k(const float* __restrict__ src, float* __restrict__ dst, int n4)
{
    int stride = gridDim.x * blockDim.x;
    for (int i = blockIdx.x*blockDim.x + threadIdx.x; i < n4; i += stride) {
        float4 v = reinterpret_cast<const float4*>(src)[i];
        v.x = tf32r(v.x); v.y = tf32r(v.y); v.z = tf32r(v.z); v.w = tf32r(v.w);
        reinterpret_cast<float4*>(dst)[i] = v;
    }
}

// ================= tf32 mma.sync GEMM =================
// C[M,N] = A[M,K] @ B[N,K]^T. M=4096, K mult of 32, N even (guarded).
// A and B both tf32-pre-rounded. CTA tile 128x128, BK=32, 3-stage cp.async
// pipeline (single __syncthreads per k-tile), 8 warps (2m x 4n), warp tile
// 64x32, 2 CTAs/SM. Grouped rasterization GROUP_M=16.
// mode: 0 plain, 1 +=Res, 2 C=tf32r(silu(Res)*acc).

#define GSTAGE 32768
#define GSMEM_DYN (3*GSTAGE)
#define GROUP_M 16

__global__ void __launch_bounds__(256, 2)
gemm_mma(const float* __restrict__ A, const float* __restrict__ Bw,
         const float* __restrict__ Res, float* __restrict__ C,
         int N, int K, int mode)
{
    extern __shared__ char smraw[];
    const int tid  = threadIdx.x;
    const int lane = tid & 31, warp = tid >> 5;
    const int wm = warp & 1, wn = warp >> 1;        // 2 x 4 warp grid
    const int T = K >> 5;
    uint32_t sbase = (uint32_t)__cvta_generic_to_shared(smraw);

    // grouped rasterization (num_pid_m = 32, divisible by GROUP_M)
    const int num_pid_n = (N + 127) >> 7;
    int pid = blockIdx.x;
    int npg = GROUP_M * num_pid_n;
    int pid_m = (pid / npg) * GROUP_M + (pid % GROUP_M);
    int pid_n = (pid % npg) / GROUP_M;
    const int bm = pid_m << 7, bn = pid_n << 7;

    // stage: A 16KB (128 rows x 128B) + B 16KB, 16B-chunk swizzled
    auto load_tile = [&](int t) {
        uint32_t s = sbase + (uint32_t)(t % 3) * GSTAGE;
        int k0 = t << 5;
        #pragma unroll
        for (int i = 0; i < 4; i++) {
            int idx = i*256 + tid, row = idx >> 3, c = idx & 7;
            uint32_t dst = s + row*128 + (uint32_t)((c ^ (row & 7)) << 4);
            asm volatile("cp.async.cg.shared.global [%0], [%1], 16;"
                         :: "r"(dst), "l"(A + (size_t)(bm + row)*K + k0 + c*4));
        }
        #pragma unroll
        for (int i = 0; i < 4; i++) {
            int idx = i*256 + tid, row = idx >> 3, c = idx & 7;
            int brow = bn + row; if (brow >= N) brow = N - 1;
            uint32_t dst = s + 16384u + row*128 + (uint32_t)((c ^ (row & 7)) << 4);
            asm volatile("cp.async.cg.shared.global [%0], [%1], 16;"
                         :: "r"(dst), "l"(Bw + (size_t)brow*K + k0 + c*4));
        }
    };

    float acc[4][4][4];
    #pragma unroll
    for (int a = 0; a < 4; a++)
        #pragma unroll
        for (int b = 0; b < 4; b++)
            #pragma unroll
            for (int c = 0; c < 4; c++) acc[a][b][c] = 0.f;

    load_tile(0);
    asm volatile("cp.async.commit_group;" ::: "memory");
    load_tile(1);
    asm volatile("cp.async.commit_group;" ::: "memory");

    for (int t = 0; t < T; t++) {
        // groups outstanding at loop top: {t, t+1} (one commit per iter below)
        asm volatile("cp.async.wait_group 1;" ::: "memory");   // tile t resident
        __syncthreads();   // all warps done computing t-1 -> buffer (t-1)%3 free
        if (t + 2 < T) load_tile(t + 2);
        asm volatile("cp.async.commit_group;" ::: "memory");   // commit (maybe empty)

        uint32_t as = sbase + (uint32_t)(t % 3) * GSTAGE;
        uint32_t bs = as + 16384u;

        #pragma unroll
        for (int kk = 0; kk < 4; kk++) {
            // A fragments: 4 m-tiles via ldmatrix.x4
            uint32_t af[4][4];
            #pragma unroll
            for (int mt = 0; mt < 4; mt++) {
                int m  = wm*64 + mt*16 + (lane & 7) + ((lane >> 3) & 1) * 8;
                int kc = kk*2 + (lane >> 4);
                uint32_t addr = as + m*128 + (uint32_t)((kc ^ (m & 7)) << 4);
                asm volatile("ldmatrix.sync.aligned.m8n8.x4.shared.b16 {%0,%1,%2,%3}, [%4];"
                             : "=r"(af[mt][0]), "=r"(af[mt][1]),
                               "=r"(af[mt][2]), "=r"(af[mt][3]) : "r"(addr));
            }
            #pragma unroll
            for (int nt = 0; nt < 4; nt++) {
                // B pair via one ldmatrix.x2 (pre-rounded: no cvt needed)
                int nrow = wn*32 + nt*8 + (lane & 7);
                int bc = kk*2 + ((lane >> 3) & 1);
                uint32_t baddr = bs + nrow*128 + (uint32_t)((bc ^ (nrow & 7)) << 4);
                uint32_t b0, b1;
                asm volatile("ldmatrix.sync.aligned.m8n8.x2.shared.b16 {%0,%1}, [%2];"
                             : "=r"(b0), "=r"(b1) : "r"(baddr));
                #pragma unroll
                for (int mt = 0; mt < 4; mt++) {
                    asm volatile(
                        "mma.sync.aligned.m16n8k8.row.col.f32.tf32.tf32.f32 "
                        "{%0,%1,%2,%3}, {%4,%5,%6,%7}, {%8,%9}, {%0,%1,%2,%3};"
                        : "+f"(acc[mt][nt][0]), "+f"(acc[mt][nt][1]),
                          "+f"(acc[mt][nt][2]), "+f"(acc[mt][nt][3])
                        : "r"(af[mt][0]), "r"(af[mt][1]), "r"(af[mt][2]), "r"(af[mt][3]),
                          "r"(b0), "r"(b1));
                }
            }
        }
    }

    // epilogue
    #pragma unroll
    for (int mt = 0; mt < 4; mt++) {
        int r0 = bm + wm*64 + mt*16 + (lane >> 2);
        #pragma unroll
        for (int nt = 0; nt < 4; nt++) {
            int c0 = bn + wn*32 + nt*8 + 2*(lane & 3);
            if (c0 < N) {
                float2 v0 = make_float2(acc[mt][nt][0], acc[mt][nt][1]);
                float2 v1 = make_float2(acc[mt][nt][2], acc[mt][nt][3]);
                if (mode == 1) {
                    float2 q0 = *reinterpret_cast<const float2*>(Res + (size_t)r0*N + c0);
                    float2 q1 = *reinterpret_cast<const float2*>(Res + (size_t)(r0+8)*N + c0);
                    v0.x += q0.x; v0.y += q0.y; v1.x += q1.x; v1.y += q1.y;
                } else if (mode == 2) {
                    float2 g0 = *reinterpret_cast<const float2*>(Res + (size_t)r0*N + c0);
                    float2 g1 = *reinterpret_cast<const float2*>(Res + (size_t)(r0+8)*N + c0);
                    v0.x = tf32r(v0.x * (g0.x / (1.f + expf(-g0.x))));
                    v0.y = tf32r(v0.y * (g0.y / (1.f + expf(-g0.y))));
                    v1.x = tf32r(v1.x * (g1.x / (1.f + expf(-g1.x))));
                    v1.y = tf32r(v1.y * (g1.y / (1.f + expf(-g1.y))));
                }
                *reinterpret_cast<float2*>(C + (size_t)r0*N + c0)     = v0;
                *reinterpret_cast<float2*>(C + (size_t)(r0+8)*N + c0) = v1;
            }
        }
    }
}

static inline int gemm_grid(int N) { return 32 * ((N + 127) >> 7); }

// ---------------- RMSNorm (output tf32-rounded: feeds GEMM A operands) ----------------
__global__ void rmsnorm_k(const float* __restrict__ x, const float* __restrict__ w,
                          float* __restrict__ o)
{
    int t = blockIdx.x;
    const float* xr = x + (size_t)t*DM;
    float s = 0.f;
    for (int i = threadIdx.x; i < DM; i += 256) { float v = xr[i]; s += v*v; }
    __shared__ float red[256];
    red[threadIdx.x] = s; __syncthreads();
    for (int st = 128; st > 0; st >>= 1) {
        if (threadIdx.x < st) red[threadIdx.x] += red[threadIdx.x + st];
        __syncthreads();
    }
    float inv = rsqrtf(red[0] / (float)DM + 1e-5f);
    float* orow = o + (size_t)t*DM;
    for (int i = threadIdx.x; i < DM; i += 256) orow[i] = tf32r(xr[i]*inv*w[i]);
}

// ---------------- fused depthwise causal conv1d+SiLU and dt/softplus ----------------
// blockIdx.x in [0,24): conv channels; blockIdx.x == 24: dt for this token
__global__ void convdt_k(const float* __restrict__ zx, const float* __restrict__ cw,
                         const float* __restrict__ cb, const float* __restrict__ dtb,
                         const float* __restrict__ Alog,
                         float* __restrict__ xbc, float* __restrict__ dto,
                         float* __restrict__ ao)
{
    int t = blockIdx.y;
    if (blockIdx.x < 24) {
        int c = blockIdx.x*256 + threadIdx.x;   // < 6144
        int l = t & (LSEQ - 1);
        const float* base = zx + (size_t)t*PROJ + 4096 + c;
        float w0 = cw[c*4+0], w1 = cw[c*4+1], w2 = cw[c*4+2], w3 = cw[c*4+3];
        float acc = cb[c] + w3*base[0];
        if (l >= 1) acc += w2*base[-(ptrdiff_t)PROJ];
        if (l >= 2) acc += w1*base[-(ptrdiff_t)(2*PROJ)];
        if (l >= 3) acc += w0*base[-(ptrdiff_t)(3*PROJ)];
        float sv = acc / (1.f + expf(-acc));
        xbc[(size_t)t*CONVD + c] = sv;
    } else if (threadIdx.x < NH) {
        int h = threadIdx.x;
        float raw = zx[(size_t)t*PROJ + 10240 + h] + dtb[h];
        float dt = (raw > 20.f) ? raw : log1pf(expf(raw));
        dto[t*NH + h] = dt;
        ao[t*NH + h]  = -expf(Alog[h]) * dt;
    }
}

// ---------------- SSD stage 1: per (b,chunk,head) ----------------
__global__ void __launch_bounds__(256)
ssd1_k(const float* __restrict__ xbc, const float* __restrict__ dtv,
       const float* __restrict__ av, const float* __restrict__ Dv,
       float* __restrict__ Y, float* __restrict__ cso,
       float* __restrict__ gmo, float* __restrict__ states)
{
    extern __shared__ float sm[];
    float* att = sm;                 // 128*129 = 16512
    float* t1  = att + 128*129;      // 4224
    float* t2  = t1 + 4224;          // 4224
    float* cs  = t2 + 4224;          // 128
    float* dts = cs + 128;           // 128
    __shared__ float wsum[4];

    int blk = blockIdx.x;
    int h = blk & 31, ch = (blk >> 5) & 15, b = blk >> 9;
    int t0 = b*LSEQ + ch*128;
    int g  = h >> 2;
    int tid = threadIdx.x;
    int tx = tid & 15, ty = tid >> 4;

    float v = 0.f;
    if (tid < 128) {
        dts[tid] = dtv[(size_t)(t0+tid)*NH + h];
        v = av[(size_t)(t0+tid)*NH + h];
        #pragma unroll
        for (int off = 1; off < 32; off <<= 1) {
            float n = __shfl_up_sync(0xffffffffu, v, off);
            if ((tid & 31) >= off) v += n;
        }
        if ((tid & 31) == 31) wsum[tid >> 5] = v;
    }
    __syncthreads();
    if (tid < 128) {
        float add = 0.f;
        for (int w = 0; w < (tid >> 5); w++) add += wsum[w];
        float c = v + add;
        cs[tid] = c;
        cso[blk*128 + tid] = c;
    }
    __syncthreads();
    if (tid == 0) gmo[blk] = expf(cs[127]);

    const float* Cbase = xbc + 2048 + h*128;
    const float* Bbase = xbc + 1024 + g*128;
    const float* Xbase = xbc + g*128;

    float acc[8][8];
    #pragma unroll
    for (int i = 0; i < 8; i++)
        #pragma unroll
        for (int j = 0; j < 8; j++) acc[i][j] = 0.f;
    for (int nt = 0; nt < 4; nt++) {
        #pragma unroll
        for (int i = 0; i < 16; i++) {
            int idx = tid + i*256;
            int q = idx >> 5, n = idx & 31;
            t1[q*33+n] = Cbase[(size_t)(t0+q)*CONVD + nt*32 + n];
            t2[q*33+n] = Bbase[(size_t)(t0+q)*CONVD + nt*32 + n];
        }
        __syncthreads();
        #pragma unroll
        for (int n = 0; n < 32; n++) {
            float cr[8], br[8];
            #pragma unroll
            for (int i = 0; i < 8; i++) cr[i] = t1[(ty*8+i)*33 + n];
            #pragma unroll
            for (int j = 0; j < 8; j++) br[j] = t2[(tx*8+j)*33 + n];
            #pragma unroll
            for (int i = 0; i < 8; i++)
                #pragma unroll
                for (int j = 0; j < 8; j++)
                    acc[i][j] = fmaf(cr[i], br[j], acc[i][j]);
        }
        __syncthreads();
    }
    #pragma unroll
    for (int i = 0; i < 8; i++) {
        int q = ty*8 + i;
        #pragma unroll
        for (int j = 0; j < 8; j++) {
            int k = tx*8 + j;
            float f = (q >= k) ? expf(cs[q] - cs[k]) * dts[k] : 0.f;
            att[q*129 + k] = acc[i][j] * f;
        }
    }
    __syncthreads();

    #pragma unroll
    for (int i = 0; i < 8; i++)
        #pragma unroll
        for (int j = 0; j < 8; j++) acc[i][j] = 0.f;
    for (int kt = 0; kt < 4; kt++) {
        #pragma unroll
        for (int i = 0; i < 16; i++) {
            int idx = tid + i*256;
            int k = idx >> 7, p = idx & 127;
            t1[k*129 + p] = Xbase[(size_t)(t0 + kt*32 + k)*CONVD + p];
        }
        __syncthreads();
        #pragma unroll
        for (int k = 0; k < 32; k++) {
            float ar[8], xr[8];
            #pragma unroll
            for (int i = 0; i < 8; i++) ar[i] = att[(ty*8+i)*129 + kt*32 + k];
            #pragma unroll
            for (int j = 0; j < 8; j++) xr[j] = t1[k*129 + tx*8 + j];
            #pragma unroll
            for (int i = 0; i < 8; i++)
                #pragma unroll
                for (int j = 0; j < 8; j++)
                    acc[i][j] = fmaf(ar[i], xr[j], acc[i][j]);
        }
        __syncthreads();
    }
    float Dh = Dv[h];
    #pragma unroll
    for (int i = 0; i < 8; i++) {
        int q = ty*8 + i; int trow = t0 + q;
        #pragma unroll
        for (int j = 0; j < 8; j++) {
            int p = tx*8 + j;
            float xv = Xbase[(size_t)trow*CONVD + p];
            Y[(size_t)trow*DIN + h*128 + p] = acc[i][j] + Dh*xv;
        }
    }
    __syncthreads();

    #pragma unroll
    for (int i = 0; i < 8; i++)
        #pragma unroll
        for (int j = 0; j < 8; j++) acc[i][j] = 0.f;
    float clast = cs[127];
    for (int qt = 0; qt < 4; qt++) {
        #pragma unroll
        for (int i = 0; i < 16; i++) {
            int idx = tid + i*256;
            int q = idx >> 7, p = idx & 127;
            int qq = qt*32 + q;
            float w = expf(clast - cs[qq]) * dts[qq];
            t1[q*129 + p] = w * Xbase[(size_t)(t0+qq)*CONVD + p];
            t2[q*129 + p] = Bbase[(size_t)(t0+qq)*CONVD + p];
        }
        __syncthreads();
        #pragma unroll
        for (int k = 0; k < 32; k++) {
            float xr[8], br[8];
            #pragma unroll
            for (int i = 0; i < 8; i++) xr[i] = t1[k*129 + ty*8 + i];
            #pragma unroll
            for (int j = 0; j < 8; j++) br[j] = t2[k*129 + tx*8 + j];
            #pragma unroll
            for (int i = 0; i < 8; i++)
                #pragma unroll
                for (int j = 0; j < 8; j++)
                    acc[i][j] = fmaf(xr[i], br[j], acc[i][j]);
        }
        __syncthreads();
    }
    size_t sbase = (size_t)blk*HP*HN;
    #pragma unroll
    for (int i = 0; i < 8; i++)
        #pragma unroll
        for (int j = 0; j < 8; j++)
            states[sbase + (size_t)(ty*8+i)*HN + tx*8 + j] = acc[i][j];
}

// ---------------- inter-chunk recurrence ----------------
__global__ void scan_k(const float* __restrict__ states, const float* __restrict__ gm,
                       float* __restrict__ prev)
{
    int bh = blockIdx.x;
    int b = bh >> 5, h = bh & 31;
    int e0 = threadIdx.x;
    float S[16];
    #pragma unroll
    for (int e = 0; e < 16; e++) S[e] = 0.f;
    for (int ch = 0; ch < NCH; ch++) {
        int blk = (b*NCH + ch)*NH + h;
        float gv = gm[blk];
        size_t base = (size_t)blk*HP*HN;
        #pragma unroll
        for (int e = 0; e < 16; e++) {
            int idx = e0 + e*1024;
            prev[base + idx] = S[e];
            S[e] = gv*S[e] + states[base + idx];
        }
    }
}

// ---------------- SSD stage 2 (+ fused silu(z) gating, tf32-rounded output) ----------------
__global__ void __launch_bounds__(256)
ssd2_k(const float* __restrict__ xbc, const float* __restrict__ prev,
       const float* __restrict__ csv, const float* __restrict__ zx,
       float* __restrict__ Y)
{
    __shared__ float t1[128*33];
    __shared__ float t2[128*33];
    __shared__ float cs[128];
    int blk = blockIdx.x;
    int h = blk & 31, ch = (blk >> 5) & 15, b = blk >> 9;
    int t0 = b*LSEQ + ch*128;
    int tid = threadIdx.x, tx = tid & 15, ty = tid >> 4;
    if (tid < 128) cs[tid] = csv[blk*128 + tid];
    float acc[8][8];
    #pragma unroll
    for (int i = 0; i < 8; i++)
        #pragma unroll
        for (int j = 0; j < 8; j++) acc[i][j] = 0.f;
    const float* Cbase = xbc + 2048 + h*128;
    size_t pbase = (size_t)blk*HP*HN;
    for (int nt = 0; nt < 4; nt++) {
        #pragma unroll
        for (int i = 0; i < 16; i++) {
            int idx = tid + i*256;
            int r = idx >> 5, n = idx & 31;
            t1[r*33+n] = Cbase[(size_t)(t0+r)*CONVD + nt*32 + n];
            t2[r*33+n] = prev[pbase + (size_t)r*HN + nt*32 + n];
        }
        __syncthreads();
        #pragma unroll
        for (int n = 0; n < 32; n++) {
            float cr[8], pr[8];
            #pragma unroll
            for (int i = 0; i < 8; i++) cr[i] = t1[(ty*8+i)*33 + n];
            #pragma unroll
            for (int j = 0; j < 8; j++) pr[j] = t2[(tx*8+j)*33 + n];
            #pragma unroll
            for (int i = 0; i < 8; i++)
                #pragma unroll
                for (int j = 0; j < 8; j++)
                    acc[i][j] = fmaf(cr[i], pr[j], acc[i][j]);
        }
        __syncthreads();
    }
    #pragma unroll
    for (int i = 0; i < 8; i++) {
        int q = ty*8 + i;
        float eq = expf(cs[q]);
        #pragma unroll
        for (int j = 0; j < 8; j++) {
            int p = tx*8 + j;
            size_t off = (size_t)(t0+q)*DIN + h*128 + p;
            float z = zx[(size_t)(t0+q)*PROJ + h*128 + p];
            float s = z / (1.f + expf(-z));
            Y[off] = tf32r((Y[off] + eq * acc[i][j]) * s);
        }
    }
}

// ---------------- launcher ----------------
extern "C" void kernel_launch(void* const* d_in, const int* in_sizes, int n_in,
                              void* d_out, int out_size)
{
    const float* hidden = (const float*)d_in[0];
    const float* w_in   = (const float*)d_in[1];
    const float* conv_w = (const float*)d_in[2];
    const float* conv_b = (const float*)d_in[3];
    const float* A_log  = (const float*)d_in[4];
    const float* Dv     = (const float*)d_in[5];
    const float* dt_b   = (const float*)d_in[6];
    const float* w_out  = (const float*)d_in[7];
    const float* ln1    = (const float*)d_in[8];
    const float* ln2    = (const float*)d_in[9];
    const float* gate_w = (const float*)d_in[10];
    const float* up_w   = (const float*)d_in[11];
    const float* down_w = (const float*)d_in[12];
    float* out = (float*)d_out;

    float *hnorm, *zx, *xbc, *dt, *av, *cs, *gm, *st, *pv, *Y, *h, *h2, *ga, *up;
    float *winr, *woutr, *gater, *upr, *downr;
    cudaGetSymbolAddress((void**)&hnorm, d_hnorm);
    cudaGetSymbolAddress((void**)&zx,    d_zx);
    cudaGetSymbolAddress((void**)&xbc,   d_xbc);
    cudaGetSymbolAddress((void**)&dt,    d_dt);
    cudaGetSymbolAddress((void**)&av,    d_av);
    cudaGetSymbolAddress((void**)&cs,    d_cs);
    cudaGetSymbolAddress((void**)&gm,    d_gm);
    cudaGetSymbolAddress((void**)&st,    d_states);
    cudaGetSymbolAddress((void**)&pv,    d_prev);
    cudaGetSymbolAddress((void**)&Y,     d_Y);
    cudaGetSymbolAddress((void**)&h,     d_h);
    cudaGetSymbolAddress((void**)&h2,    d_h2);
    cudaGetSymbolAddress((void**)&ga,    d_ga);
    cudaGetSymbolAddress((void**)&up,    d_up);
    cudaGetSymbolAddress((void**)&winr,  d_win_r);
    cudaGetSymbolAddress((void**)&woutr, d_wout_r);
    cudaGetSymbolAddress((void**)&gater, d_gate_r);
    cudaGetSymbolAddress((void**)&upr,   d_upw_r);
    cudaGetSymbolAddress((void**)&downr, d_down_r);

    cudaFuncSetAttribute(gemm_mma, cudaFuncAttributeMaxDynamicSharedMemorySize, GSMEM_DYN);

    // 0) pre-round weights to tf32
    round_tf32_k<<<1024, 256>>>(w_in,   winr,  (PROJ*DM)/4);
    round_tf32_k<<<1024, 256>>>(w_out,  woutr, (DM*DIN)/4);
    round_tf32_k<<<1024, 256>>>(gate_w, gater, (INTERD*DM)/4);
    round_tf32_k<<<1024, 256>>>(up_w,   upr,   (INTERD*DM)/4);
    round_tf32_k<<<1024, 256>>>(down_w, downr, (DM*INTERD)/4);

    // 1) pre-norm (tf32-rounded output)
    rmsnorm_k<<<TKN, 256>>>(hidden, ln1, hnorm);
    // 2) in_proj
    gemm_mma<<<gemm_grid(PROJ), 256, GSMEM_DYN>>>(hnorm, winr, nullptr, zx, PROJ, DM, 0);
    // 3+4) fused depthwise causal conv + SiLU and dt/a
    convdt_k<<<dim3(25, TKN), 256>>>(zx, conv_w, conv_b, dt_b, A_log, xbc, dt, av);
    // 5) SSD stage 1
    int smem1 = (128*129 + 4224 + 4224 + 128 + 128) * 4;
    cudaFuncSetAttribute(ssd1_k, cudaFuncAttributeMaxDynamicSharedMemorySize, smem1);
    ssd1_k<<<NBLK, 256, smem1>>>(xbc, dt, av, Dv, Y, cs, gm, st);
    // 6) inter-chunk recurrence
    scan_k<<<NB*NH, 1024>>>(st, gm, pv);
    // 7) SSD stage 2 + fused silu(z) gating
    ssd2_k<<<NBLK, 256>>>(xbc, pv, cs, zx, Y);
    // 8) out_proj + residual
    gemm_mma<<<gemm_grid(DM), 256, GSMEM_DYN>>>(Y, woutr, hidden, h, DM, DIN, 1);
    // 9) second norm (tf32-rounded output)
    rmsnorm_k<<<TKN, 256>>>(h, ln2, h2);
    // 10) MLP: gate GEMM, then up GEMM with fused silu(gate)*up
    gemm_mma<<<gemm_grid(INTERD), 256, GSMEM_DYN>>>(h2, gater, nullptr, ga, INTERD, DM, 0);
    gemm_mma<<<gemm_grid(INTERD), 256, GSMEM_DYN>>>(h2, upr, ga, up, INTERD, DM, 2);
    // 11) down_proj + residual -> out
    gemm_mma<<<gemm_grid(DM), 256, GSMEM_DYN>>>(up, downr, h, out, DM, INTERD, 1);
}

// round 9
// speedup vs baseline: 1.1967x; 1.0556x over previous
#include <cuda_runtime.h>
#include <math.h>
#include <stdint.h>

// ---------------- fixed shapes ----------------
#define TKN   4096
#define NB    2
#define LSEQ  2048
#define DM    4096
#define DXB   1024
#define DIN   4096
#define NH    32
#define HP    128
#define HN    128
#define PROJ  10272
#define CONVD 6144
#define INTERD 14336
#define NCH   16
#define NBLK  (NB*NCH*NH)

// ---------------- scratch ----------------
__device__ float d_hnorm[TKN*DM];
__device__ float d_zx[TKN*PROJ];
__device__ float d_xbc[TKN*CONVD];
__device__ float d_dt[TKN*NH];
__device__ float d_av[TKN*NH];
__device__ float d_cs[NBLK*128];
__device__ float d_gm[NBLK];
__device__ float d_states[(size_t)NBLK*HP*HN];
__device__ float d_prev[(size_t)NBLK*HP*HN];
__device__ float d_Y[TKN*DIN];
__device__ float d_h[TKN*DM];
__device__ float d_h2[TKN*DM];
__device__ float d_ga[(size_t)TKN*INTERD];
__device__ float d_up[(size_t)TKN*INTERD];
__device__ float d_win_r[(size_t)PROJ*DM];
__device__ float d_wout_r[(size_t)DM*DIN];
__device__ float d_gate_r[(size_t)INTERD*DM];
__device__ float d_upw_r[(size_t)INTERD*DM];
__device__ float d_down_r[(size_t)DM*INTERD];

static __device__ __forceinline__ float tf32r(float x) {
    uint32_t u; asm("cvt.rna.tf32.f32 %0, %1;" : "=r"(u) : "f"(x));
    return __uint_as_float(u);
}

__global__ void round_tf32_k(const float* __restrict__ src, float* __restrict__ dst, int n4)
{
    int stride = gridDim.x * blockDim.x;
    for (int i = blockIdx.x*blockDim.x + threadIdx.x; i < n4; i += stride) {
        float4 v = reinterpret_cast<const float4*>(src)[i];
        v.x = tf32r(v.x); v.y = tf32r(v.y); v.z = tf32r(v.z); v.w = tf32r(v.w);
        reinterpret_cast<float4*>(dst)[i] = v;
    }
}

// ---------- shared helpers for mma tiles ----------
// swizzled 128x128 fp32 tile: sub-tiled by contraction-chunks of 32 (16KB each)
static __device__ __forceinline__ uint32_t swaddr(uint32_t base, int r, int c) {
    uint32_t sub   = (uint32_t)((c >> 5) << 14);
    uint32_t chunk = (uint32_t)(((((c & 31) >> 2)) ^ (r & 7)) << 4);
    uint32_t byte  = (uint32_t)((c & 3) << 2);
    return base + sub + (uint32_t)(r << 7) + chunk + byte;
}
static __device__ __forceinline__ void load_tile128(uint32_t sb, const float* g,
                                                    int grs, int tid) {
    #pragma unroll
    for (int i = 0; i < 16; i++) {
        int idx = i*256 + tid;
        int r = idx >> 5, c = (idx & 31) << 2;
        asm volatile("cp.async.cg.shared.global [%0], [%1], 16;"
                     :: "r"(swaddr(sb, r, c)), "l"(g + (size_t)r*grs + c));
    }
}
// D[128x128] += A[128x128] * B[128x128]^T over 128-contraction, warp (wm,wn), 8 warps 2x4
static __device__ __forceinline__ void mma_tile128(uint32_t abase, uint32_t bbase,
                                                   float (&acc)[4][4][4],
                                                   int wm, int wn, int lane) {
    #pragma unroll
    for (int t = 0; t < 4; t++) {
        uint32_t as = abase + (uint32_t)(t << 14), bs = bbase + (uint32_t)(t << 14);
        #pragma unroll
        for (int kk = 0; kk < 4; kk++) {
            uint32_t af[4][4];
            #pragma unroll
            for (int mt = 0; mt < 4; mt++) {
                int m  = wm*64 + mt*16 + (lane & 7) + ((lane >> 3) & 1) * 8;
                int kc = kk*2 + (lane >> 4);
                uint32_t addr = as + (uint32_t)(m << 7) + (uint32_t)((kc ^ (m & 7)) << 4);
                asm volatile("ldmatrix.sync.aligned.m8n8.x4.shared.b16 {%0,%1,%2,%3}, [%4];"
                             : "=r"(af[mt][0]), "=r"(af[mt][1]),
                               "=r"(af[mt][2]), "=r"(af[mt][3]) : "r"(addr));
            }
            #pragma unroll
            for (int nt = 0; nt < 4; nt++) {
                int nrow = wn*32 + nt*8 + (lane & 7);
                int bc = kk*2 + ((lane >> 3) & 1);
                uint32_t baddr = bs + (uint32_t)(nrow << 7) + (uint32_t)((bc ^ (nrow & 7)) << 4);
                uint32_t b0, b1;
                asm volatile("ldmatrix.sync.aligned.m8n8.x2.shared.b16 {%0,%1}, [%2];"
                             : "=r"(b0), "=r"(b1) : "r"(baddr));
                #pragma unroll
                for (int mt = 0; mt < 4; mt++) {
                    asm volatile(
                        "mma.sync.aligned.m16n8k8.row.col.f32.tf32.tf32.f32 "
                        "{%0,%1,%2,%3}, {%4,%5,%6,%7}, {%8,%9}, {%0,%1,%2,%3};"
                        : "+f"(acc[mt][nt][0]), "+f"(acc[mt][nt][1]),
                          "+f"(acc[mt][nt][2]), "+f"(acc[mt][nt][3])
                        : "r"(af[mt][0]), "r"(af[mt][1]), "r"(af[mt][2]), "r"(af[mt][3]),
                          "r"(b0), "r"(b1));
                }
            }
        }
    }
}
// transpose swizzled [r][c] tile -> swizzled [c][r] tile
static __device__ __forceinline__ void transpose128(uint32_t src, uint32_t dst,
                                                    int warp, int lane) {
    #pragma unroll
    for (int ks = 0; ks < 4; ks++) {
        int k = ks*32 + lane;
        #pragma unroll
        for (int j = 0; j < 16; j++) {
            int p = warp*16 + j;
            float v;
            asm volatile("ld.shared.f32 %0, [%1];" : "=f"(v) : "r"(swaddr(src, k, p)));
            asm volatile("st.shared.f32 [%0], %1;" :: "r"(swaddr(dst, p, k)), "f"(v));
        }
    }
}
static __device__ __forceinline__ void zero_acc(float (&acc)[4][4][4]) {
    #pragma unroll
    for (int a = 0; a < 4; a++)
        #pragma unroll
        for (int b = 0; b < 4; b++)
            #pragma unroll
            for (int c = 0; c < 4; c++) acc[a][b][c] = 0.f;
}

// ================= tf32 mma.sync dense GEMM (R6, proven) =================
#define GSTAGE 32768
#define GSMEM_DYN (3*GSTAGE)
#define GROUP_M 16

__global__ void __launch_bounds__(256, 2)
gemm_mma(const float* __restrict__ A, const float* __restrict__ Bw,
         const float* __restrict__ Res, float* __restrict__ C,
         int N, int K, int mode)
{
    extern __shared__ char smraw[];
    const int tid  = threadIdx.x;
    const int lane = tid & 31, warp = tid >> 5;
    const int wm = warp & 1, wn = warp >> 1;
    const int T = K >> 5;
    uint32_t sbase = (uint32_t)__cvta_generic_to_shared(smraw);

    const int num_pid_n = (N + 127) >> 7;
    int pid = blockIdx.x;
    int npg = GROUP_M * num_pid_n;
    int pid_m = (pid / npg) * GROUP_M + (pid % GROUP_M);
    int pid_n = (pid % npg) / GROUP_M;
    const int bm = pid_m << 7, bn = pid_n << 7;

    auto load_tile = [&](int t) {
        uint32_t s = sbase + (uint32_t)(t % 3) * GSTAGE;
        int k0 = t << 5;
        #pragma unroll
        for (int i = 0; i < 4; i++) {
            int idx = i*256 + tid, row = idx >> 3, c = idx & 7;
            uint32_t dst = s + row*128 + (uint32_t)((c ^ (row & 7)) << 4);
            asm volatile("cp.async.cg.shared.global [%0], [%1], 16;"
                         :: "r"(dst), "l"(A + (size_t)(bm + row)*K + k0 + c*4));
        }
        #pragma unroll
        for (int i = 0; i < 4; i++) {
            int idx = i*256 + tid, row = idx >> 3, c = idx & 7;
            int brow = bn + row; if (brow >= N) brow = N - 1;
            uint32_t dst = s + 16384u + row*128 + (uint32_t)((c ^ (row & 7)) << 4);
            asm volatile("cp.async.cg.shared.global [%0], [%1], 16;"
                         :: "r"(dst), "l"(Bw + (size_t)brow*K + k0 + c*4));
        }
    };

    float acc[4][4][4];
    zero_acc(acc);

    load_tile(0);
    asm volatile("cp.async.commit_group;" ::: "memory");
    load_tile(1);
    asm volatile("cp.async.commit_group;" ::: "memory");

    for (int t = 0; t < T; t++) {
        asm volatile("cp.async.wait_group 1;" ::: "memory");
        __syncthreads();
        if (t + 2 < T) load_tile(t + 2);
        asm volatile("cp.async.commit_group;" ::: "memory");

        uint32_t as = sbase + (uint32_t)(t % 3) * GSTAGE;
        uint32_t bs = as + 16384u;

        #pragma unroll
        for (int kk = 0; kk < 4; kk++) {
            uint32_t af[4][4];
            #pragma unroll
            for (int mt = 0; mt < 4; mt++) {
                int m  = wm*64 + mt*16 + (lane & 7) + ((lane >> 3) & 1) * 8;
                int kc = kk*2 + (lane >> 4);
                uint32_t addr = as + m*128 + (uint32_t)((kc ^ (m & 7)) << 4);
                asm volatile("ldmatrix.sync.aligned.m8n8.x4.shared.b16 {%0,%1,%2,%3}, [%4];"
                             : "=r"(af[mt][0]), "=r"(af[mt][1]),
                               "=r"(af[mt][2]), "=r"(af[mt][3]) : "r"(addr));
            }
            #pragma unroll
            for (int nt = 0; nt < 4; nt++) {
                int nrow = wn*32 + nt*8 + (lane & 7);
                int bc = kk*2 + ((lane >> 3) & 1);
                uint32_t baddr = bs + nrow*128 + (uint32_t)((bc ^ (nrow & 7)) << 4);
                uint32_t b0, b1;
                asm volatile("ldmatrix.sync.aligned.m8n8.x2.shared.b16 {%0,%1}, [%2];"
                             : "=r"(b0), "=r"(b1) : "r"(baddr));
                #pragma unroll
                for (int mt = 0; mt < 4; mt++) {
                    asm volatile(
                        "mma.sync.aligned.m16n8k8.row.col.f32.tf32.tf32.f32 "
                        "{%0,%1,%2,%3}, {%4,%5,%6,%7}, {%8,%9}, {%0,%1,%2,%3};"
                        : "+f"(acc[mt][nt][0]), "+f"(acc[mt][nt][1]),
                          "+f"(acc[mt][nt][2]), "+f"(acc[mt][nt][3])
                        : "r"(af[mt][0]), "r"(af[mt][1]), "r"(af[mt][2]), "r"(af[mt][3]),
                          "r"(b0), "r"(b1));
                }
            }
        }
    }

    #pragma unroll
    for (int mt = 0; mt < 4; mt++) {
        int r0 = bm + wm*64 + mt*16 + (lane >> 2);
        #pragma unroll
        for (int nt = 0; nt < 4; nt++) {
            int c0 = bn + wn*32 + nt*8 + 2*(lane & 3);
            if (c0 < N) {
                float2 v0 = make_float2(acc[mt][nt][0], acc[mt][nt][1]);
                float2 v1 = make_float2(acc[mt][nt][2], acc[mt][nt][3]);
                if (mode == 1) {
                    float2 q0 = *reinterpret_cast<const float2*>(Res + (size_t)r0*N + c0);
                    float2 q1 = *reinterpret_cast<const float2*>(Res + (size_t)(r0+8)*N + c0);
                    v0.x += q0.x; v0.y += q0.y; v1.x += q1.x; v1.y += q1.y;
                } else if (mode == 2) {
                    float2 g0 = *reinterpret_cast<const float2*>(Res + (size_t)r0*N + c0);
                    float2 g1 = *reinterpret_cast<const float2*>(Res + (size_t)(r0+8)*N + c0);
                    v0.x = tf32r(v0.x * (g0.x / (1.f + expf(-g0.x))));
                    v0.y = tf32r(v0.y * (g0.y / (1.f + expf(-g0.y))));
                    v1.x = tf32r(v1.x * (g1.x / (1.f + expf(-g1.x))));
                    v1.y = tf32r(v1.y * (g1.y / (1.f + expf(-g1.y))));
                }
                *reinterpret_cast<float2*>(C + (size_t)r0*N + c0)     = v0;
                *reinterpret_cast<float2*>(C + (size_t)(r0+8)*N + c0) = v1;
            }
        }
    }
}

static inline int gemm_grid(int N) { return 32 * ((N + 127) >> 7); }

// ---------------- RMSNorm ----------------
__global__ void rmsnorm_k(const float* __restrict__ x, const float* __restrict__ w,
                          float* __restrict__ o)
{
    int t = blockIdx.x;
    const float* xr = x + (size_t)t*DM;
    float s = 0.f;
    for (int i = threadIdx.x; i < DM; i += 256) { float v = xr[i]; s += v*v; }
    __shared__ float red[256];
    red[threadIdx.x] = s; __syncthreads();
    for (int st = 128; st > 0; st >>= 1) {
        if (threadIdx.x < st) red[threadIdx.x] += red[threadIdx.x + st];
        __syncthreads();
    }
    float inv = rsqrtf(red[0] / (float)DM + 1e-5f);
    float* orow = o + (size_t)t*DM;
    for (int i = threadIdx.x; i < DM; i += 256) orow[i] = tf32r(xr[i]*inv*w[i]);
}

// ---------------- fused conv+SiLU (tf32-rounded out) and dt ----------------
__global__ void convdt_k(const float* __restrict__ zx, const float* __restrict__ cw,
                         const float* __restrict__ cb, const float* __restrict__ dtb,
                         const float* __restrict__ Alog,
                         float* __restrict__ xbc, float* __restrict__ dto,
                         float* __restrict__ ao)
{
    int t = blockIdx.y;
    if (blockIdx.x < 24) {
        int c = blockIdx.x*256 + threadIdx.x;
        int l = t & (LSEQ - 1);
        const float* base = zx + (size_t)t*PROJ + 4096 + c;
        float w0 = cw[c*4+0], w1 = cw[c*4+1], w2 = cw[c*4+2], w3 = cw[c*4+3];
        float acc = cb[c] + w3*base[0];
        if (l >= 1) acc += w2*base[-(ptrdiff_t)PROJ];
        if (l >= 2) acc += w1*base[-(ptrdiff_t)(2*PROJ)];
        if (l >= 3) acc += w0*base[-(ptrdiff_t)(3*PROJ)];
        float sv = acc / (1.f + expf(-acc));
        xbc[(size_t)t*CONVD + c] = tf32r(sv);
    } else if (threadIdx.x < NH) {
        int h = threadIdx.x;
        float raw = zx[(size_t)t*PROJ + 10240 + h] + dtb[h];
        float dt = (raw > 20.f) ? raw : log1pf(expf(raw));
        dto[t*NH + h] = dt;
        ao[t*NH + h]  = -expf(Alog[h]) * dt;
    }
}

// ---------------- SSD stage 1 (tensor cores): per (b,chunk,head) ----------------
#define SSD1_SMEM 196608
__global__ void __launch_bounds__(256)
ssd1_k(const float* __restrict__ xbc, const float* __restrict__ dtv,
       const float* __restrict__ av, const float* __restrict__ Dv,
       float* __restrict__ Y, float* __restrict__ cso,
       float* __restrict__ gmo, float* __restrict__ states)
{
    extern __shared__ float dyn[];
    __shared__ float cs[128], dts[128], wv[128], wsum[4];
    uint32_t sb = (uint32_t)__cvta_generic_to_shared(dyn);
    uint32_t O_C = sb, O_B = sb + 65536u, O_X = sb + 131072u;

    int blk = blockIdx.x;
    int h = blk & 31, ch = (blk >> 5) & 15, b = blk >> 9;
    int t0 = b*LSEQ + ch*128;
    int g  = h >> 2;
    int tid = threadIdx.x, lane = tid & 31, warp = tid >> 5;
    int wm = warp & 1, wn = warp >> 1;

    const float* gC = xbc + (size_t)t0*CONVD + 2048 + h*128;
    const float* gB = xbc + (size_t)t0*CONVD + 1024 + g*128;
    const float* gX = xbc + (size_t)t0*CONVD + g*128;
    load_tile128(O_C, gC, CONVD, tid);
    load_tile128(O_B, gB, CONVD, tid);
    load_tile128(O_X, gX, CONVD, tid);
    asm volatile("cp.async.commit_group;" ::: "memory");

    // cumsum of a over chunk
    float v = 0.f;
    if (tid < 128) {
        dts[tid] = dtv[(size_t)(t0+tid)*NH + h];
        v = av[(size_t)(t0+tid)*NH + h];
        #pragma unroll
        for (int off = 1; off < 32; off <<= 1) {
            float n = __shfl_up_sync(0xffffffffu, v, off);
            if (lane >= off) v += n;
        }
        if (lane == 31) wsum[tid >> 5] = v;
    }
    __syncthreads();
    if (tid < 128) {
        float add = 0.f;
        for (int w = 0; w < (tid >> 5); w++) add += wsum[w];
        float c = v + add;
        cs[tid] = c;
        cso[blk*128 + tid] = c;
    }
    __syncthreads();
    if (tid < 128) wv[tid] = __expf(cs[127] - cs[tid]) * dts[tid];
    if (tid == 0) gmo[blk] = expf(cs[127]);

    asm volatile("cp.async.wait_group 0;" ::: "memory");
    __syncthreads();

    // ---- MMA1: att = C (q,n) x B (k,n)^T ----
    float acc[4][4][4];
    zero_acc(acc);
    mma_tile128(O_C, O_B, acc, wm, wn, lane);
    __syncthreads();                       // all reads of sC done
    transpose128(O_X, O_C, warp, lane);    // X -> X^T into O_C
    __syncthreads();
    // write masked/scaled att into O_X (tf32)
    #pragma unroll
    for (int mt = 0; mt < 4; mt++) {
        int r0 = wm*64 + mt*16 + (lane >> 2);
        #pragma unroll
        for (int nt = 0; nt < 4; nt++) {
            int c0 = wn*32 + nt*8 + 2*(lane & 3);
            #pragma unroll
            for (int e = 0; e < 4; e++) {
                int q = r0 + (e >> 1)*8, k = c0 + (e & 1);
                float f = (q >= k) ? __expf(cs[q] - cs[k]) * dts[k] : 0.f;
                float val = tf32r(acc[mt][nt][e] * f);
                asm volatile("st.shared.f32 [%0], %1;" :: "r"(swaddr(O_X, q, k)), "f"(val));
            }
        }
    }
    __syncthreads();
    // ---- MMA2: Yd = att (q,k) x X^T (p,k)^T ----
    zero_acc(acc);
    mma_tile128(O_X, O_C, acc, wm, wn, lane);
    float Dh = Dv[h];
    #pragma unroll
    for (int mt = 0; mt < 4; mt++) {
        int r0 = wm*64 + mt*16 + (lane >> 2);
        #pragma unroll
        for (int nt = 0; nt < 4; nt++) {
            int c0 = wn*32 + nt*8 + 2*(lane & 3);
            #pragma unroll
            for (int e = 0; e < 4; e++) {
                int q = r0 + (e >> 1)*8, p = c0 + (e & 1);
                float xv;
                asm volatile("ld.shared.f32 %0, [%1];" : "=f"(xv) : "r"(swaddr(O_C, p, q)));
                Y[(size_t)(t0+q)*DIN + h*128 + p] = acc[mt][nt][e] + Dh*xv;
            }
        }
    }
    __syncthreads();                       // att reads done (O_X free)
    transpose128(O_B, O_X, warp, lane);    // B -> B^T into O_X
    // scale X^T by w (tf32) in place
    #pragma unroll
    for (int ks = 0; ks < 4; ks++) {
        int k = ks*32 + lane;
        float wk = wv[k];
        #pragma unroll
        for (int j = 0; j < 16; j++) {
            int p = warp*16 + j;
            float xv;
            asm volatile("ld.shared.f32 %0, [%1];" : "=f"(xv) : "r"(swaddr(O_C, p, k)));
            xv = tf32r(xv * wk);
            asm volatile("st.shared.f32 [%0], %1;" :: "r"(swaddr(O_C, p, k)), "f"(xv));
        }
    }
    __syncthreads();
    // ---- MMA3: states = (wX)^T (p,q) x B^T (n,q)^T ----
    zero_acc(acc);
    mma_tile128(O_C, O_X, acc, wm, wn, lane);
    size_t sbase = (size_t)blk*HP*HN;
    #pragma unroll
    for (int mt = 0; mt < 4; mt++) {
        int r0 = wm*64 + mt*16 + (lane >> 2);
        #pragma unroll
        for (int nt = 0; nt < 4; nt++) {
            int c0 = wn*32 + nt*8 + 2*(lane & 3);
            *reinterpret_cast<float2*>(states + sbase + (size_t)r0*HN + c0)
                = make_float2(acc[mt][nt][0], acc[mt][nt][1]);
            *reinterpret_cast<float2*>(states + sbase + (size_t)(r0+8)*HN + c0)
                = make_float2(acc[mt][nt][2], acc[mt][nt][3]);
        }
    }
}

// ---------------- inter-chunk recurrence (prev written tf32) ----------------
__global__ void scan_k(const float* __restrict__ states, const float* __restrict__ gm,
                       float* __restrict__ prev)
{
    int bh = blockIdx.x;
    int b = bh >> 5, h = bh & 31;
    int e0 = threadIdx.x;
    float S[16];
    #pragma unroll
    for (int e = 0; e < 16; e++) S[e] = 0.f;
    for (int ch = 0; ch < NCH; ch++) {
        int blk = (b*NCH + ch)*NH + h;
        float gv = gm[blk];
        size_t base = (size_t)blk*HP*HN;
        #pragma unroll
        for (int e = 0; e < 16; e++) {
            int idx = e0 + e*1024;
            prev[base + idx] = tf32r(S[e]);
            S[e] = gv*S[e] + states[base + idx];
        }
    }
}

// ---------------- SSD stage 2 (tensor cores) + fused silu(z) gating ----------------
#define SSD2_SMEM 131072
__global__ void __launch_bounds__(256)
ssd2_k(const float* __restrict__ xbc, const float* __restrict__ prev,
       const float* __restrict__ csv, const float* __restrict__ zx,
       float* __restrict__ Y)
{
    extern __shared__ float dyn[];
    __shared__ float cs[128];
    uint32_t sb = (uint32_t)__cvta_generic_to_shared(dyn);
    uint32_t O_C = sb, O_P = sb + 65536u;

    int blk = blockIdx.x;
    int h = blk & 31, ch = (blk >> 5) & 15, b = blk >> 9;
    int t0 = b*LSEQ + ch*128;
    int tid = threadIdx.x, lane = tid & 31, warp = tid >> 5;
    int wm = warp & 1, wn = warp >> 1;

    const float* gC = xbc + (size_t)t0*CONVD + 2048 + h*128;
    size_t pbase = (size_t)blk*HP*HN;
    load_tile128(O_C, gC, CONVD, tid);
    load_tile128(O_P, prev + pbase, HN, tid);
    asm volatile("cp.async.commit_group;" ::: "memory");
    if (tid < 128) cs[tid] = csv[blk*128 + tid];
    asm volatile("cp.async.wait_group 0;" ::: "memory");
    __syncthreads();

    float acc[4][4][4];
    zero_acc(acc);
    mma_tile128(O_C, O_P, acc, wm, wn, lane);

    #pragma unroll
    for (int mt = 0; mt < 4; mt++) {
        int r0 = wm*64 + mt*16 + (lane >> 2);
        float eq0 = __expf(cs[r0]), eq1 = __expf(cs[r0 + 8]);
        #pragma unroll
        for (int nt = 0; nt < 4; nt++) {
            int c0 = wn*32 + nt*8 + 2*(lane & 3);
            #pragma unroll
            for (int half = 0; half < 2; half++) {
                int q = r0 + half*8;
                float eq = half ? eq1 : eq0;
                size_t off = (size_t)(t0+q)*DIN + h*128 + c0;
                float2 yv = *reinterpret_cast<float2*>(Y + off);
                float2 zv = *reinterpret_cast<const float2*>(zx + (size_t)(t0+q)*PROJ + h*128 + c0);
                float s0 = zv.x / (1.f + expf(-zv.x));
                float s1 = zv.y / (1.f + expf(-zv.y));
                float a0 = acc[mt][nt][half*2+0], a1 = acc[mt][nt][half*2+1];
                yv.x = tf32r((yv.x + eq*a0) * s0);
                yv.y = tf32r((yv.y + eq*a1) * s1);
                *reinterpret_cast<float2*>(Y + off) = yv;
            }
        }
    }
}

// ---------------- launcher ----------------
extern "C" void kernel_launch(void* const* d_in, const int* in_sizes, int n_in,
                              void* d_out, int out_size)
{
    const float* hidden = (const float*)d_in[0];
    const float* w_in   = (const float*)d_in[1];
    const float* conv_w = (const float*)d_in[2];
    const float* conv_b = (const float*)d_in[3];
    const float* A_log  = (const float*)d_in[4];
    const float* Dv     = (const float*)d_in[5];
    const float* dt_b   = (const float*)d_in[6];
    const float* w_out  = (const float*)d_in[7];
    const float* ln1    = (const float*)d_in[8];
    const float* ln2    = (const float*)d_in[9];
    const float* gate_w = (const float*)d_in[10];
    const float* up_w   = (const float*)d_in[11];
    const float* down_w = (const float*)d_in[12];
    float* out = (float*)d_out;

    float *hnorm, *zx, *xbc, *dt, *av, *cs, *gm, *st, *pv, *Y, *h, *h2, *ga, *up;
    float *winr, *woutr, *gater, *upr, *downr;
    cudaGetSymbolAddress((void**)&hnorm, d_hnorm);
    cudaGetSymbolAddress((void**)&zx,    d_zx);
    cudaGetSymbolAddress((void**)&xbc,   d_xbc);
    cudaGetSymbolAddress((void**)&dt,    d_dt);
    cudaGetSymbolAddress((void**)&av,    d_av);
    cudaGetSymbolAddress((void**)&cs,    d_cs);
    cudaGetSymbolAddress((void**)&gm,    d_gm);
    cudaGetSymbolAddress((void**)&st,    d_states);
    cudaGetSymbolAddress((void**)&pv,    d_prev);
    cudaGetSymbolAddress((void**)&Y,     d_Y);
    cudaGetSymbolAddress((void**)&h,     d_h);
    cudaGetSymbolAddress((void**)&h2,    d_h2);
    cudaGetSymbolAddress((void**)&ga,    d_ga);
    cudaGetSymbolAddress((void**)&up,    d_up);
    cudaGetSymbolAddress((void**)&winr,  d_win_r);
    cudaGetSymbolAddress((void**)&woutr, d_wout_r);
    cudaGetSymbolAddress((void**)&gater, d_gate_r);
    cudaGetSymbolAddress((void**)&upr,   d_upw_r);
    cudaGetSymbolAddress((void**)&downr, d_down_r);

    cudaFuncSetAttribute(gemm_mma, cudaFuncAttributeMaxDynamicSharedMemorySize, GSMEM_DYN);
    cudaFuncSetAttribute(ssd1_k, cudaFuncAttributeMaxDynamicSharedMemorySize, SSD1_SMEM);
    cudaFuncSetAttribute(ssd2_k, cudaFuncAttributeMaxDynamicSharedMemorySize, SSD2_SMEM);

    // 0) pre-round weights to tf32
    round_tf32_k<<<1024, 256>>>(w_in,   winr,  (PROJ*DM)/4);
    round_tf32_k<<<1024, 256>>>(w_out,  woutr, (DM*DIN)/4);
    round_tf32_k<<<1024, 256>>>(gate_w, gater, (INTERD*DM)/4);
    round_tf32_k<<<1024, 256>>>(up_w,   upr,   (INTERD*DM)/4);
    round_tf32_k<<<1024, 256>>>(down_w, downr, (DM*INTERD)/4);

    // 1) pre-norm
    rmsnorm_k<<<TKN, 256>>>(hidden, ln1, hnorm);
    // 2) in_proj
    gemm_mma<<<gemm_grid(PROJ), 256, GSMEM_DYN>>>(hnorm, winr, nullptr, zx, PROJ, DM, 0);
    // 3+4) fused conv + dt
    convdt_k<<<dim3(25, TKN), 256>>>(zx, conv_w, conv_b, dt_b, A_log, xbc, dt, av);
    // 5) SSD stage 1 (tensor cores)
    ssd1_k<<<NBLK, 256, SSD1_SMEM>>>(xbc, dt, av, Dv, Y, cs, gm, st);
    // 6) inter-chunk recurrence
    scan_k<<<NB*NH, 1024>>>(st, gm, pv);
    // 7) SSD stage 2 (tensor cores) + gating
    ssd2_k<<<NBLK, 256, SSD2_SMEM>>>(xbc, pv, cs, zx, Y);
    // 8) out_proj + residual
    gemm_mma<<<gemm_grid(DM), 256, GSMEM_DYN>>>(Y, woutr, hidden, h, DM, DIN, 1);
    // 9) second norm
    rmsnorm_k<<<TKN, 256>>>(h, ln2, h2);
    // 10) MLP
    gemm_mma<<<gemm_grid(INTERD), 256, GSMEM_DYN>>>(h2, gater, nullptr, ga, INTERD, DM, 0);
    gemm_mma<<<gemm_grid(INTERD), 256, GSMEM_DYN>>>(h2, upr, ga, up, INTERD, DM, 2);
    // 11) down_proj + residual -> out
    gemm_mma<<<gemm_grid(DM), 256, GSMEM_DYN>>>(up, downr, h, out, DM, INTERD, 1);
}

// round 10
// speedup vs baseline: 2.2384x; 1.8705x over previous
#include <cuda_runtime.h>
#include <cuda_fp16.h>
#include <math.h>
#include <stdint.h>

// ---------------- fixed shapes ----------------
#define TKN   4096
#define NB    2
#define LSEQ  2048
#define DM    4096
#define DXB   1024
#define DIN   4096
#define NH    32
#define HP    128
#define HN    128
#define PROJ  10272
#define CONVD 6144
#define INTERD 14336
#define NCH   16
#define NBLK  (NB*NCH*NH)

// ---------------- scratch ----------------
__device__ __half d_hnormh[TKN*DM];
__device__ float  d_zx[TKN*PROJ];
__device__ float  d_xbc[TKN*CONVD];
__device__ float  d_dt[TKN*NH];
__device__ float  d_av[TKN*NH];
__device__ float  d_cs[NBLK*128];
__device__ float  d_gm[NBLK];
__device__ float  d_states[(size_t)NBLK*HP*HN];
__device__ float  d_prev[(size_t)NBLK*HP*HN];
__device__ float  d_Y[TKN*DIN];
__device__ __half d_Yh[TKN*DIN];
__device__ float  d_h[TKN*DM];
__device__ __half d_h2h[TKN*DM];
__device__ float  d_ga[(size_t)TKN*INTERD];
__device__ __half d_uph[(size_t)TKN*INTERD];
// fp16 weights
__device__ __half d_win_h[(size_t)PROJ*DM];
__device__ __half d_wout_h[(size_t)DM*DIN];
__device__ __half d_gate_h[(size_t)INTERD*DM];
__device__ __half d_upw_h[(size_t)INTERD*DM];
__device__ __half d_down_h[(size_t)DM*INTERD];

static __device__ __forceinline__ float tf32r(float x) {
    uint32_t u; asm("cvt.rna.tf32.f32 %0, %1;" : "=r"(u) : "f"(x));
    return __uint_as_float(u);
}

// ---------------- convert weights fp32 -> fp16 ----------------
__global__ void to_half_k(const float* __restrict__ src, __half* __restrict__ dst, int n4)
{
    int stride = gridDim.x * blockDim.x;
    for (int i = blockIdx.x*blockDim.x + threadIdx.x; i < n4; i += stride) {
        float4 v = reinterpret_cast<const float4*>(src)[i];
        __half2 h0 = __floats2half2_rn(v.x, v.y);
        __half2 h1 = __floats2half2_rn(v.z, v.w);
        reinterpret_cast<__half2*>(dst)[2*i]   = h0;
        reinterpret_cast<__half2*>(dst)[2*i+1] = h1;
    }
}

// ---------- tf32 mma tile helpers (SSD path, proven R8) ----------
static __device__ __forceinline__ uint32_t swaddr(uint32_t base, int r, int c) {
    uint32_t sub   = (uint32_t)((c >> 5) << 14);
    uint32_t chunk = (uint32_t)(((((c & 31) >> 2)) ^ (r & 7)) << 4);
    uint32_t byte  = (uint32_t)((c & 3) << 2);
    return base + sub + (uint32_t)(r << 7) + chunk + byte;
}
static __device__ __forceinline__ void load_tile128(uint32_t sb, const float* g,
                                                    int grs, int tid) {
    #pragma unroll
    for (int i = 0; i < 16; i++) {
        int idx = i*256 + tid;
        int r = idx >> 5, c = (idx & 31) << 2;
        asm volatile("cp.async.cg.shared.global [%0], [%1], 16;"
                     :: "r"(swaddr(sb, r, c)), "l"(g + (size_t)r*grs + c));
    }
}
static __device__ __forceinline__ void mma_tile128(uint32_t abase, uint32_t bbase,
                                                   float (&acc)[4][4][4],
                                                   int wm, int wn, int lane) {
    #pragma unroll
    for (int t = 0; t < 4; t++) {
        uint32_t as = abase + (uint32_t)(t << 14), bs = bbase + (uint32_t)(t << 14);
        #pragma unroll
        for (int kk = 0; kk < 4; kk++) {
            uint32_t af[4][4];
            #pragma unroll
            for (int mt = 0; mt < 4; mt++) {
                int m  = wm*64 + mt*16 + (lane & 7) + ((lane >> 3) & 1) * 8;
                int kc = kk*2 + (lane >> 4);
                uint32_t addr = as + (uint32_t)(m << 7) + (uint32_t)((kc ^ (m & 7)) << 4);
                asm volatile("ldmatrix.sync.aligned.m8n8.x4.shared.b16 {%0,%1,%2,%3}, [%4];"
                             : "=r"(af[mt][0]), "=r"(af[mt][1]),
                               "=r"(af[mt][2]), "=r"(af[mt][3]) : "r"(addr));
            }
            #pragma unroll
            for (int nt = 0; nt < 4; nt++) {
                int nrow = wn*32 + nt*8 + (lane & 7);
                int bc = kk*2 + ((lane >> 3) & 1);
                uint32_t baddr = bs + (uint32_t)(nrow << 7) + (uint32_t)((bc ^ (nrow & 7)) << 4);
                uint32_t b0, b1;
                asm volatile("ldmatrix.sync.aligned.m8n8.x2.shared.b16 {%0,%1}, [%2];"
                             : "=r"(b0), "=r"(b1) : "r"(baddr));
                #pragma unroll
                for (int mt = 0; mt < 4; mt++) {
                    asm volatile(
                        "mma.sync.aligned.m16n8k8.row.col.f32.tf32.tf32.f32 "
                        "{%0,%1,%2,%3}, {%4,%5,%6,%7}, {%8,%9}, {%0,%1,%2,%3};"
                        : "+f"(acc[mt][nt][0]), "+f"(acc[mt][nt][1]),
                          "+f"(acc[mt][nt][2]), "+f"(acc[mt][nt][3])
                        : "r"(af[mt][0]), "r"(af[mt][1]), "r"(af[mt][2]), "r"(af[mt][3]),
                          "r"(b0), "r"(b1));
                }
            }
        }
    }
}
static __device__ __forceinline__ void transpose128(uint32_t src, uint32_t dst,
                                                    int warp, int lane) {
    #pragma unroll
    for (int ks = 0; ks < 4; ks++) {
        int k = ks*32 + lane;
        #pragma unroll
        for (int j = 0; j < 16; j++) {
            int p = warp*16 + j;
            float v;
            asm volatile("ld.shared.f32 %0, [%1];" : "=f"(v) : "r"(swaddr(src, k, p)));
            asm volatile("st.shared.f32 [%0], %1;" :: "r"(swaddr(dst, p, k)), "f"(v));
        }
    }
}
static __device__ __forceinline__ void zero_acc(float (&acc)[4][4][4]) {
    #pragma unroll
    for (int a = 0; a < 4; a++)
        #pragma unroll
        for (int b = 0; b < 4; b++)
            #pragma unroll
            for (int c = 0; c < 4; c++) acc[a][b][c] = 0.f;
}

// ================= fp16 mma.sync dense GEMM =================
// C[M,N] = A[M,K] @ B[N,K]^T, fp16 inputs, fp32 accumulate.
// CTA tile 128x128, BK=64 (128B/row, same swizzle as tf32 version), 3-stage
// cp.async, 8 warps (2m x 4n), warp tile 64x32, 2 CTAs/SM, GROUP_M=16.
// mode: 0 -> Cf plain; 1 -> Cf = acc + Res; 2 -> Ch = half(silu(Res)*acc).

#define GSTAGE 32768
#define GSMEM_DYN (3*GSTAGE)
#define GROUP_M 16

__global__ void __launch_bounds__(256, 2)
gemm_h(const __half* __restrict__ A, const __half* __restrict__ Bw,
       const float* __restrict__ Res, float* __restrict__ Cf,
       __half* __restrict__ Ch, int N, int K, int mode)
{
    extern __shared__ char smraw[];
    const int tid  = threadIdx.x;
    const int lane = tid & 31, warp = tid >> 5;
    const int wm = warp & 1, wn = warp >> 1;
    const int T = K >> 6;
    uint32_t sbase = (uint32_t)__cvta_generic_to_shared(smraw);

    const int num_pid_n = (N + 127) >> 7;
    int pid = blockIdx.x;
    int npg = GROUP_M * num_pid_n;
    int pid_m = (pid / npg) * GROUP_M + (pid % GROUP_M);
    int pid_n = (pid % npg) / GROUP_M;
    const int bm = pid_m << 7, bn = pid_n << 7;

    // stage: A 16KB (128 rows x 64 halves = 128B/row) + B 16KB, 16B-chunk swizzled
    auto load_tile = [&](int t) {
        uint32_t s = sbase + (uint32_t)(t % 3) * GSTAGE;
        int k0 = t << 6;
        #pragma unroll
        for (int i = 0; i < 4; i++) {
            int idx = i*256 + tid, row = idx >> 3, c = idx & 7;
            uint32_t dst = s + row*128 + (uint32_t)((c ^ (row & 7)) << 4);
            asm volatile("cp.async.cg.shared.global [%0], [%1], 16;"
                         :: "r"(dst), "l"(A + (size_t)(bm + row)*K + k0 + c*8));
        }
        #pragma unroll
        for (int i = 0; i < 4; i++) {
            int idx = i*256 + tid, row = idx >> 3, c = idx & 7;
            int brow = bn + row; if (brow >= N) brow = N - 1;
            uint32_t dst = s + 16384u + row*128 + (uint32_t)((c ^ (row & 7)) << 4);
            asm volatile("cp.async.cg.shared.global [%0], [%1], 16;"
                         :: "r"(dst), "l"(Bw + (size_t)brow*K + k0 + c*8));
        }
    };

    float acc[4][4][4];
    zero_acc(acc);

    load_tile(0);
    asm volatile("cp.async.commit_group;" ::: "memory");
    load_tile(1);
    asm volatile("cp.async.commit_group;" ::: "memory");

    for (int t = 0; t < T; t++) {
        asm volatile("cp.async.wait_group 1;" ::: "memory");
        __syncthreads();
        if (t + 2 < T) load_tile(t + 2);
        asm volatile("cp.async.commit_group;" ::: "memory");

        uint32_t as = sbase + (uint32_t)(t % 3) * GSTAGE;
        uint32_t bs = as + 16384u;

        // 4 k16-chunks of the 64-wide k-tile; chunk kk covers halves [16kk,16kk+16)
        #pragma unroll
        for (int kk = 0; kk < 4; kk++) {
            uint32_t af[4][4];
            #pragma unroll
            for (int mt = 0; mt < 4; mt++) {
                int m  = wm*64 + mt*16 + (lane & 7) + ((lane >> 3) & 1) * 8;
                int kc = kk*2 + (lane >> 4);            // 16B chunk = 8 halves
                uint32_t addr = as + m*128 + (uint32_t)((kc ^ (m & 7)) << 4);
                asm volatile("ldmatrix.sync.aligned.m8n8.x4.shared.b16 {%0,%1,%2,%3}, [%4];"
                             : "=r"(af[mt][0]), "=r"(af[mt][1]),
                               "=r"(af[mt][2]), "=r"(af[mt][3]) : "r"(addr));
            }
            #pragma unroll
            for (int nt = 0; nt < 4; nt++) {
                int nrow = wn*32 + nt*8 + (lane & 7);
                int bc = kk*2 + ((lane >> 3) & 1);
                uint32_t baddr = bs + nrow*128 + (uint32_t)((bc ^ (nrow & 7)) << 4);
                uint32_t b0, b1;
                asm volatile("ldmatrix.sync.aligned.m8n8.x2.shared.b16 {%0,%1}, [%2];"
                             : "=r"(b0), "=r"(b1) : "r"(baddr));
                #pragma unroll
                for (int mt = 0; mt < 4; mt++) {
                    asm volatile(
                        "mma.sync.aligned.m16n8k16.row.col.f32.f16.f16.f32 "
                        "{%0,%1,%2,%3}, {%4,%5,%6,%7}, {%8,%9}, {%0,%1,%2,%3};"
                        : "+f"(acc[mt][nt][0]), "+f"(acc[mt][nt][1]),
                          "+f"(acc[mt][nt][2]), "+f"(acc[mt][nt][3])
                        : "r"(af[mt][0]), "r"(af[mt][1]), "r"(af[mt][2]), "r"(af[mt][3]),
                          "r"(b0), "r"(b1));
                }
            }
        }
    }

    // epilogue
    #pragma unroll
    for (int mt = 0; mt < 4; mt++) {
        int r0 = bm + wm*64 + mt*16 + (lane >> 2);
        #pragma unroll
        for (int nt = 0; nt < 4; nt++) {
            int c0 = bn + wn*32 + nt*8 + 2*(lane & 3);
            if (c0 < N) {
                float2 v0 = make_float2(acc[mt][nt][0], acc[mt][nt][1]);
                float2 v1 = make_float2(acc[mt][nt][2], acc[mt][nt][3]);
                if (mode == 2) {
                    float2 g0 = *reinterpret_cast<const float2*>(Res + (size_t)r0*N + c0);
                    float2 g1 = *reinterpret_cast<const float2*>(Res + (size_t)(r0+8)*N + c0);
                    v0.x *= g0.x / (1.f + expf(-g0.x));
                    v0.y *= g0.y / (1.f + expf(-g0.y));
                    v1.x *= g1.x / (1.f + expf(-g1.x));
                    v1.y *= g1.y / (1.f + expf(-g1.y));
                    *reinterpret_cast<__half2*>(Ch + (size_t)r0*N + c0)
                        = __floats2half2_rn(v0.x, v0.y);
                    *reinterpret_cast<__half2*>(Ch + (size_t)(r0+8)*N + c0)
                        = __floats2half2_rn(v1.x, v1.y);
                } else {
                    if (mode == 1) {
                        float2 q0 = *reinterpret_cast<const float2*>(Res + (size_t)r0*N + c0);
                        float2 q1 = *reinterpret_cast<const float2*>(Res + (size_t)(r0+8)*N + c0);
                        v0.x += q0.x; v0.y += q0.y; v1.x += q1.x; v1.y += q1.y;
                    }
                    *reinterpret_cast<float2*>(Cf + (size_t)r0*N + c0)     = v0;
                    *reinterpret_cast<float2*>(Cf + (size_t)(r0+8)*N + c0) = v1;
                }
            }
        }
    }
}

static inline int gemm_grid(int N) { return 32 * ((N + 127) >> 7); }

// ---------------- RMSNorm (fp16 output: feeds GEMM A operands) ----------------
__global__ void rmsnorm_k(const float* __restrict__ x, const float* __restrict__ w,
                          __half* __restrict__ o)
{
    int t = blockIdx.x;
    const float* xr = x + (size_t)t*DM;
    float s = 0.f;
    for (int i = threadIdx.x; i < DM; i += 256) { float v = xr[i]; s += v*v; }
    __shared__ float red[256];
    red[threadIdx.x] = s; __syncthreads();
    for (int st = 128; st > 0; st >>= 1) {
        if (threadIdx.x < st) red[threadIdx.x] += red[threadIdx.x + st];
        __syncthreads();
    }
    float inv = rsqrtf(red[0] / (float)DM + 1e-5f);
    __half* orow = o + (size_t)t*DM;
    for (int i = threadIdx.x; i < DM; i += 256) orow[i] = __float2half_rn(xr[i]*inv*w[i]);
}

// ---------------- fused conv+SiLU (tf32-rounded out) and dt ----------------
__global__ void convdt_k(const float* __restrict__ zx, const float* __restrict__ cw,
                         const float* __restrict__ cb, const float* __restrict__ dtb,
                         const float* __restrict__ Alog,
                         float* __restrict__ xbc, float* __restrict__ dto,
                         float* __restrict__ ao)
{
    int t = blockIdx.y;
    if (blockIdx.x < 24) {
        int c = blockIdx.x*256 + threadIdx.x;
        int l = t & (LSEQ - 1);
        const float* base = zx + (size_t)t*PROJ + 4096 + c;
        float w0 = cw[c*4+0], w1 = cw[c*4+1], w2 = cw[c*4+2], w3 = cw[c*4+3];
        float acc = cb[c] + w3*base[0];
        if (l >= 1) acc += w2*base[-(ptrdiff_t)PROJ];
        if (l >= 2) acc += w1*base[-(ptrdiff_t)(2*PROJ)];
        if (l >= 3) acc += w0*base[-(ptrdiff_t)(3*PROJ)];
        float sv = acc / (1.f + expf(-acc));
        xbc[(size_t)t*CONVD + c] = tf32r(sv);
    } else if (threadIdx.x < NH) {
        int h = threadIdx.x;
        float raw = zx[(size_t)t*PROJ + 10240 + h] + dtb[h];
        float dt = (raw > 20.f) ? raw : log1pf(expf(raw));
        dto[t*NH + h] = dt;
        ao[t*NH + h]  = -expf(Alog[h]) * dt;
    }
}

// ---------------- SSD stage 1 (tf32 tensor cores, proven R8) ----------------
#define SSD1_SMEM 196608
__global__ void __launch_bounds__(256)
ssd1_k(const float* __restrict__ xbc, const float* __restrict__ dtv,
       const float* __restrict__ av, const float* __restrict__ Dv,
       float* __restrict__ Y, float* __restrict__ cso,
       float* __restrict__ gmo, float* __restrict__ states)
{
    extern __shared__ float dyn[];
    __shared__ float cs[128], dts[128], wv[128], wsum[4];
    uint32_t sb = (uint32_t)__cvta_generic_to_shared(dyn);
    uint32_t O_C = sb, O_B = sb + 65536u, O_X = sb + 131072u;

    int blk = blockIdx.x;
    int h = blk & 31, ch = (blk >> 5) & 15, b = blk >> 9;
    int t0 = b*LSEQ + ch*128;
    int g  = h >> 2;
    int tid = threadIdx.x, lane = tid & 31, warp = tid >> 5;
    int wm = warp & 1, wn = warp >> 1;

    const float* gC = xbc + (size_t)t0*CONVD + 2048 + h*128;
    const float* gB = xbc + (size_t)t0*CONVD + 1024 + g*128;
    const float* gX = xbc + (size_t)t0*CONVD + g*128;
    load_tile128(O_C, gC, CONVD, tid);
    load_tile128(O_B, gB, CONVD, tid);
    load_tile128(O_X, gX, CONVD, tid);
    asm volatile("cp.async.commit_group;" ::: "memory");

    float v = 0.f;
    if (tid < 128) {
        dts[tid] = dtv[(size_t)(t0+tid)*NH + h];
        v = av[(size_t)(t0+tid)*NH + h];
        #pragma unroll
        for (int off = 1; off < 32; off <<= 1) {
            float n = __shfl_up_sync(0xffffffffu, v, off);
            if (lane >= off) v += n;
        }
        if (lane == 31) wsum[tid >> 5] = v;
    }
    __syncthreads();
    if (tid < 128) {
        float add = 0.f;
        for (int w = 0; w < (tid >> 5); w++) add += wsum[w];
        float c = v + add;
        cs[tid] = c;
        cso[blk*128 + tid] = c;
    }
    __syncthreads();
    if (tid < 128) wv[tid] = __expf(cs[127] - cs[tid]) * dts[tid];
    if (tid == 0) gmo[blk] = expf(cs[127]);

    asm volatile("cp.async.wait_group 0;" ::: "memory");
    __syncthreads();

    float acc[4][4][4];
    zero_acc(acc);
    mma_tile128(O_C, O_B, acc, wm, wn, lane);
    __syncthreads();
    transpose128(O_X, O_C, warp, lane);
    __syncthreads();
    #pragma unroll
    for (int mt = 0; mt < 4; mt++) {
        int r0 = wm*64 + mt*16 + (lane >> 2);
        #pragma unroll
        for (int nt = 0; nt < 4; nt++) {
            int c0 = wn*32 + nt*8 + 2*(lane & 3);
            #pragma unroll
            for (int e = 0; e < 4; e++) {
                int q = r0 + (e >> 1)*8, k = c0 + (e & 1);
                float f = (q >= k) ? __expf(cs[q] - cs[k]) * dts[k] : 0.f;
                float val = tf32r(acc[mt][nt][e] * f);
                asm volatile("st.shared.f32 [%0], %1;" :: "r"(swaddr(O_X, q, k)), "f"(val));
            }
        }
    }
    __syncthreads();
    zero_acc(acc);
    mma_tile128(O_X, O_C, acc, wm, wn, lane);
    float Dh = Dv[h];
    #pragma unroll
    for (int mt = 0; mt < 4; mt++) {
        int r0 = wm*64 + mt*16 + (lane >> 2);
        #pragma unroll
        for (int nt = 0; nt < 4; nt++) {
            int c0 = wn*32 + nt*8 + 2*(lane & 3);
            #pragma unroll
            for (int e = 0; e < 4; e++) {
                int q = r0 + (e >> 1)*8, p = c0 + (e & 1);
                float xv;
                asm volatile("ld.shared.f32 %0, [%1];" : "=f"(xv) : "r"(swaddr(O_C, p, q)));
                Y[(size_t)(t0+q)*DIN + h*128 + p] = acc[mt][nt][e] + Dh*xv;
            }
        }
    }
    __syncthreads();
    transpose128(O_B, O_X, warp, lane);
    #pragma unroll
    for (int ks = 0; ks < 4; ks++) {
        int k = ks*32 + lane;
        float wk = wv[k];
        #pragma unroll
        for (int j = 0; j < 16; j++) {
            int p = warp*16 + j;
            float xv;
            asm volatile("ld.shared.f32 %0, [%1];" : "=f"(xv) : "r"(swaddr(O_C, p, k)));
            xv = tf32r(xv * wk);
            asm volatile("st.shared.f32 [%0], %1;" :: "r"(swaddr(O_C, p, k)), "f"(xv));
        }
    }
    __syncthreads();
    zero_acc(acc);
    mma_tile128(O_C, O_X, acc, wm, wn, lane);
    size_t sbase = (size_t)blk*HP*HN;
    #pragma unroll
    for (int mt = 0; mt < 4; mt++) {
        int r0 = wm*64 + mt*16 + (lane >> 2);
        #pragma unroll
        for (int nt = 0; nt < 4; nt++) {
            int c0 = wn*32 + nt*8 + 2*(lane & 3);
            *reinterpret_cast<float2*>(states + sbase + (size_t)r0*HN + c0)
                = make_float2(acc[mt][nt][0], acc[mt][nt][1]);
            *reinterpret_cast<float2*>(states + sbase + (size_t)(r0+8)*HN + c0)
                = make_float2(acc[mt][nt][2], acc[mt][nt][3]);
        }
    }
}

// ---------------- inter-chunk recurrence (prev written tf32) ----------------
__global__ void scan_k(const float* __restrict__ states, const float* __restrict__ gm,
                       float* __restrict__ prev)
{
    int bh = blockIdx.x;
    int b = bh >> 5, h = bh & 31;
    int e0 = threadIdx.x;
    float S[16];
    #pragma unroll
    for (int e = 0; e < 16; e++) S[e] = 0.f;
    for (int ch = 0; ch < NCH; ch++) {
        int blk = (b*NCH + ch)*NH + h;
        float gv = gm[blk];
        size_t base = (size_t)blk*HP*HN;
        #pragma unroll
        for (int e = 0; e < 16; e++) {
            int idx = e0 + e*1024;
            prev[base + idx] = tf32r(S[e]);
            S[e] = gv*S[e] + states[base + idx];
        }
    }
}

// ---------------- SSD stage 2 (tf32 tensor cores) + gating -> fp16 Yh ----------------
#define SSD2_SMEM 131072
__global__ void __launch_bounds__(256)
ssd2_k(const float* __restrict__ xbc, const float* __restrict__ prev,
       const float* __restrict__ csv, const float* __restrict__ zx,
       const float* __restrict__ Y, __half* __restrict__ Yh)
{
    extern __shared__ float dyn[];
    __shared__ float cs[128];
    uint32_t sb = (uint32_t)__cvta_generic_to_shared(dyn);
    uint32_t O_C = sb, O_P = sb + 65536u;

    int blk = blockIdx.x;
    int h = blk & 31, ch = (blk >> 5) & 15, b = blk >> 9;
    int t0 = b*LSEQ + ch*128;
    int tid = threadIdx.x, lane = tid & 31, warp = tid >> 5;
    int wm = warp & 1, wn = warp >> 1;

    const float* gC = xbc + (size_t)t0*CONVD + 2048 + h*128;
    size_t pbase = (size_t)blk*HP*HN;
    load_tile128(O_C, gC, CONVD, tid);
    load_tile128(O_P, prev + pbase, HN, tid);
    asm volatile("cp.async.commit_group;" ::: "memory");
    if (tid < 128) cs[tid] = csv[blk*128 + tid];
    asm volatile("cp.async.wait_group 0;" ::: "memory");
    __syncthreads();

    float acc[4][4][4];
    zero_acc(acc);
    mma_tile128(O_C, O_P, acc, wm, wn, lane);

    #pragma unroll
    for (int mt = 0; mt < 4; mt++) {
        int r0 = wm*64 + mt*16 + (lane >> 2);
        float eq0 = __expf(cs[r0]), eq1 = __expf(cs[r0 + 8]);
        #pragma unroll
        for (int nt = 0; nt < 4; nt++) {
            int c0 = wn*32 + nt*8 + 2*(lane & 3);
            #pragma unroll
            for (int half = 0; half < 2; half++) {
                int q = r0 + half*8;
                float eq = half ? eq1 : eq0;
                size_t off = (size_t)(t0+q)*DIN + h*128 + c0;
                float2 yv = *reinterpret_cast<const float2*>(Y + off);
                float2 zv = *reinterpret_cast<const float2*>(zx + (size_t)(t0+q)*PROJ + h*128 + c0);
                float s0 = zv.x / (1.f + expf(-zv.x));
                float s1 = zv.y / (1.f + expf(-zv.y));
                float a0 = acc[mt][nt][half*2+0], a1 = acc[mt][nt][half*2+1];
                *reinterpret_cast<__half2*>(Yh + off)
                    = __floats2half2_rn((yv.x + eq*a0) * s0, (yv.y + eq*a1) * s1);
            }
        }
    }
}

// ---------------- launcher ----------------
extern "C" void kernel_launch(void* const* d_in, const int* in_sizes, int n_in,
                              void* d_out, int out_size)
{
    const float* hidden = (const float*)d_in[0];
    const float* w_in   = (const float*)d_in[1];
    const float* conv_w = (const float*)d_in[2];
    const float* conv_b = (const float*)d_in[3];
    const float* A_log  = (const float*)d_in[4];
    const float* Dv     = (const float*)d_in[5];
    const float* dt_b   = (const float*)d_in[6];
    const float* w_out  = (const float*)d_in[7];
    const float* ln1    = (const float*)d_in[8];
    const float* ln2    = (const float*)d_in[9];
    const float* gate_w = (const float*)d_in[10];
    const float* up_w   = (const float*)d_in[11];
    const float* down_w = (const float*)d_in[12];
    float* out = (float*)d_out;

    float *zx, *xbc, *dt, *av, *cs, *gm, *st, *pv, *Y, *h, *ga;
    __half *hnormh, *Yh, *h2h, *uph;
    __half *winh, *wouth, *gateh, *upwh, *downh;
    cudaGetSymbolAddress((void**)&hnormh, d_hnormh);
    cudaGetSymbolAddress((void**)&zx,     d_zx);
    cudaGetSymbolAddress((void**)&xbc,    d_xbc);
    cudaGetSymbolAddress((void**)&dt,     d_dt);
    cudaGetSymbolAddress((void**)&av,     d_av);
    cudaGetSymbolAddress((void**)&cs,     d_cs);
    cudaGetSymbolAddress((void**)&gm,     d_gm);
    cudaGetSymbolAddress((void**)&st,     d_states);
    cudaGetSymbolAddress((void**)&pv,     d_prev);
    cudaGetSymbolAddress((void**)&Y,      d_Y);
    cudaGetSymbolAddress((void**)&Yh,     d_Yh);
    cudaGetSymbolAddress((void**)&h,      d_h);
    cudaGetSymbolAddress((void**)&h2h,    d_h2h);
    cudaGetSymbolAddress((void**)&ga,     d_ga);
    cudaGetSymbolAddress((void**)&uph,    d_uph);
    cudaGetSymbolAddress((void**)&winh,   d_win_h);
    cudaGetSymbolAddress((void**)&wouth,  d_wout_h);
    cudaGetSymbolAddress((void**)&gateh,  d_gate_h);
    cudaGetSymbolAddress((void**)&upwh,   d_upw_h);
    cudaGetSymbolAddress((void**)&downh,  d_down_h);

    cudaFuncSetAttribute(gemm_h, cudaFuncAttributeMaxDynamicSharedMemorySize, GSMEM_DYN);
    cudaFuncSetAttribute(ssd1_k, cudaFuncAttributeMaxDynamicSharedMemorySize, SSD1_SMEM);
    cudaFuncSetAttribute(ssd2_k, cudaFuncAttributeMaxDynamicSharedMemorySize, SSD2_SMEM);

    // 0) convert weights to fp16
    to_half_k<<<1024, 256>>>(w_in,   winh,  (PROJ*DM)/4);
    to_half_k<<<1024, 256>>>(w_out,  wouth, (DM*DIN)/4);
    to_half_k<<<1024, 256>>>(gate_w, gateh, (INTERD*DM)/4);
    to_half_k<<<1024, 256>>>(up_w,   upwh,  (INTERD*DM)/4);
    to_half_k<<<1024, 256>>>(down_w, downh, (DM*INTERD)/4);

    // 1) pre-norm (fp16 output)
    rmsnorm_k<<<TKN, 256>>>(hidden, ln1, hnormh);
    // 2) in_proj (fp16 tensor cores)
    gemm_h<<<gemm_grid(PROJ), 256, GSMEM_DYN>>>(hnormh, winh, nullptr, zx, nullptr, PROJ, DM, 0);
    // 3+4) fused conv + dt
    convdt_k<<<dim3(25, TKN), 256>>>(zx, conv_w, conv_b, dt_b, A_log, xbc, dt, av);
    // 5) SSD stage 1 (tf32 tensor cores)
    ssd1_k<<<NBLK, 256, SSD1_SMEM>>>(xbc, dt, av, Dv, Y, cs, gm, st);
    // 6) inter-chunk recurrence
    scan_k<<<NB*NH, 1024>>>(st, gm, pv);
    // 7) SSD stage 2 + gating -> fp16 Yh
    ssd2_k<<<NBLK, 256, SSD2_SMEM>>>(xbc, pv, cs, zx, Y, Yh);
    // 8) out_proj + residual
    gemm_h<<<gemm_grid(DM), 256, GSMEM_DYN>>>(Yh, wouth, hidden, h, nullptr, DM, DIN, 1);
    // 9) second norm (fp16 output)
    rmsnorm_k<<<TKN, 256>>>(h, ln2, h2h);
    // 10) MLP
    gemm_h<<<gemm_grid(INTERD), 256, GSMEM_DYN>>>(h2h, gateh, nullptr, ga, nullptr, INTERD, DM, 0);
    gemm_h<<<gemm_grid(INTERD), 256, GSMEM_DYN>>>(h2h, upwh, ga, nullptr, uph, INTERD, DM, 2);
    // 11) down_proj + residual -> out
    gemm_h<<<gemm_grid(DM), 256, GSMEM_DYN>>>(uph, downh, h, out, nullptr, DM, INTERD, 1);
}

// round 11
// speedup vs baseline: 2.2399x; 1.0007x over previous
#include <cuda_runtime.h>
#include <cuda_fp16.h>
#include <math.h>
#include <stdint.h>

// ---------------- fixed shapes ----------------
#define TKN   4096
#define NB    2
#define LSEQ  2048
#define DM    4096
#define DXB   1024
#define DIN   4096
#define NH    32
#define HP    128
#define HN    128
#define PROJ  10272
#define CONVD 6144
#define INTERD 14336
#define NCH   16
#define NBLK  (NB*NCH*NH)

// ---------------- scratch ----------------
__device__ __half d_hnormh[TKN*DM];
__device__ float  d_zx[TKN*PROJ];
__device__ float  d_xbc[TKN*CONVD];
__device__ float  d_dt[TKN*NH];
__device__ float  d_av[TKN*NH];
__device__ float  d_cs[NBLK*128];
__device__ float  d_gm[NBLK];
__device__ float  d_states[(size_t)NBLK*HP*HN];
__device__ float  d_prev[(size_t)NBLK*HP*HN];
__device__ float  d_Y[TKN*DIN];
__device__ __half d_Yh[TKN*DIN];
__device__ float  d_h[TKN*DM];
__device__ __half d_h2h[TKN*DM];
__device__ __half d_uph[(size_t)TKN*INTERD];
// fp16 weights
__device__ __half d_win_h[(size_t)PROJ*DM];
__device__ __half d_wout_h[(size_t)DM*DIN];
__device__ __half d_gu_h[(size_t)2*INTERD*DM];   // row-interleaved gate/up
__device__ __half d_down_h[(size_t)DM*INTERD];

static __device__ __forceinline__ float tf32r(float x) {
    uint32_t u; asm("cvt.rna.tf32.f32 %0, %1;" : "=r"(u) : "f"(x));
    return __uint_as_float(u);
}

// ---------------- convert weights fp32 -> fp16 ----------------
__global__ void to_half_k(const float* __restrict__ src, __half* __restrict__ dst, int n4)
{
    int stride = gridDim.x * blockDim.x;
    for (int i = blockIdx.x*blockDim.x + threadIdx.x; i < n4; i += stride) {
        float4 v = reinterpret_cast<const float4*>(src)[i];
        reinterpret_cast<__half2*>(dst)[2*i]   = __floats2half2_rn(v.x, v.y);
        reinterpret_cast<__half2*>(dst)[2*i+1] = __floats2half2_rn(v.z, v.w);
    }
}

// ---------------- interleave gate/up rows -> fp16 (even=gate, odd=up) ----------------
__global__ void interleave_half_k(const float* __restrict__ g, const float* __restrict__ u,
                                  __half* __restrict__ dst, int n4)
{
    int stride = gridDim.x * blockDim.x;
    for (int i = blockIdx.x*blockDim.x + threadIdx.x; i < n4; i += stride) {
        int r  = i >> 10;             // DM/4 = 1024 float4 per row
        int c4 = i & 1023;
        const float* src = ((r & 1) ? u : g) + (size_t)(r >> 1)*DM + c4*4;
        float4 v = *reinterpret_cast<const float4*>(src);
        __half* drow = dst + (size_t)r*DM + c4*4;
        *reinterpret_cast<__half2*>(drow)     = __floats2half2_rn(v.x, v.y);
        *reinterpret_cast<__half2*>(drow + 2) = __floats2half2_rn(v.z, v.w);
    }
}

// ---------- tf32 mma tile helpers (SSD path, proven) ----------
static __device__ __forceinline__ uint32_t swaddr(uint32_t base, int r, int c) {
    uint32_t sub   = (uint32_t)((c >> 5) << 14);
    uint32_t chunk = (uint32_t)(((((c & 31) >> 2)) ^ (r & 7)) << 4);
    uint32_t byte  = (uint32_t)((c & 3) << 2);
    return base + sub + (uint32_t)(r << 7) + chunk + byte;
}
static __device__ __forceinline__ void load_tile128(uint32_t sb, const float* g,
                                                    int grs, int tid) {
    #pragma unroll
    for (int i = 0; i < 16; i++) {
        int idx = i*256 + tid;
        int r = idx >> 5, c = (idx & 31) << 2;
        asm volatile("cp.async.cg.shared.global [%0], [%1], 16;"
                     :: "r"(swaddr(sb, r, c)), "l"(g + (size_t)r*grs + c));
    }
}
static __device__ __forceinline__ void mma_tile128(uint32_t abase, uint32_t bbase,
                                                   float (&acc)[4][4][4],
                                                   int wm, int wn, int lane) {
    #pragma unroll
    for (int t = 0; t < 4; t++) {
        uint32_t as = abase + (uint32_t)(t << 14), bs = bbase + (uint32_t)(t << 14);
        #pragma unroll
        for (int kk = 0; kk < 4; kk++) {
            uint32_t af[4][4];
            #pragma unroll
            for (int mt = 0; mt < 4; mt++) {
                int m  = wm*64 + mt*16 + (lane & 7) + ((lane >> 3) & 1) * 8;
                int kc = kk*2 + (lane >> 4);
                uint32_t addr = as + (uint32_t)(m << 7) + (uint32_t)((kc ^ (m & 7)) << 4);
                asm volatile("ldmatrix.sync.aligned.m8n8.x4.shared.b16 {%0,%1,%2,%3}, [%4];"
                             : "=r"(af[mt][0]), "=r"(af[mt][1]),
                               "=r"(af[mt][2]), "=r"(af[mt][3]) : "r"(addr));
            }
            #pragma unroll
            for (int nt = 0; nt < 4; nt++) {
                int nrow = wn*32 + nt*8 + (lane & 7);
                int bc = kk*2 + ((lane >> 3) & 1);
                uint32_t baddr = bs + (uint32_t)(nrow << 7) + (uint32_t)((bc ^ (nrow & 7)) << 4);
                uint32_t b0, b1;
                asm volatile("ldmatrix.sync.aligned.m8n8.x2.shared.b16 {%0,%1}, [%2];"
                             : "=r"(b0), "=r"(b1) : "r"(baddr));
                #pragma unroll
                for (int mt = 0; mt < 4; mt++) {
                    asm volatile(
                        "mma.sync.aligned.m16n8k8.row.col.f32.tf32.tf32.f32 "
                        "{%0,%1,%2,%3}, {%4,%5,%6,%7}, {%8,%9}, {%0,%1,%2,%3};"
                        : "+f"(acc[mt][nt][0]), "+f"(acc[mt][nt][1]),
                          "+f"(acc[mt][nt][2]), "+f"(acc[mt][nt][3])
                        : "r"(af[mt][0]), "r"(af[mt][1]), "r"(af[mt][2]), "r"(af[mt][3]),
                          "r"(b0), "r"(b1));
                }
            }
        }
    }
}
static __device__ __forceinline__ void transpose128(uint32_t src, uint32_t dst,
                                                    int warp, int lane) {
    #pragma unroll
    for (int ks = 0; ks < 4; ks++) {
        int k = ks*32 + lane;
        #pragma unroll
        for (int j = 0; j < 16; j++) {
            int p = warp*16 + j;
            float v;
            asm volatile("ld.shared.f32 %0, [%1];" : "=f"(v) : "r"(swaddr(src, k, p)));
            asm volatile("st.shared.f32 [%0], %1;" :: "r"(swaddr(dst, p, k)), "f"(v));
        }
    }
}
static __device__ __forceinline__ void zero_acc(float (&acc)[4][4][4]) {
    #pragma unroll
    for (int a = 0; a < 4; a++)
        #pragma unroll
        for (int b = 0; b < 4; b++)
            #pragma unroll
            for (int c = 0; c < 4; c++) acc[a][b][c] = 0.f;
}

// ================= fp16 mma.sync dense GEMM =================
// C[M,N] = A[M,K] @ B[N,K]^T, fp16 in, fp32 accum. 128x128 tile, BK=64,
// 3-stage cp.async, 8 warps 2x4, 2 CTAs/SM, GROUP_M=16.
// mode 0: Cf = acc. mode 1: Cf = acc + Res.
// mode 3: interleaved gate/up -> Ch[r][c/2] = half(silu(acc_even)*acc_odd), row stride N/2.

#define GSTAGE 32768
#define GSMEM_DYN (3*GSTAGE)
#define GROUP_M 16

__global__ void __launch_bounds__(256, 2)
gemm_h(const __half* __restrict__ A, const __half* __restrict__ Bw,
       const float* __restrict__ Res, float* __restrict__ Cf,
       __half* __restrict__ Ch, int N, int K, int mode)
{
    extern __shared__ char smraw[];
    const int tid  = threadIdx.x;
    const int lane = tid & 31, warp = tid >> 5;
    const int wm = warp & 1, wn = warp >> 1;
    const int T = K >> 6;
    uint32_t sbase = (uint32_t)__cvta_generic_to_shared(smraw);

    const int num_pid_n = (N + 127) >> 7;
    int pid = blockIdx.x;
    int npg = GROUP_M * num_pid_n;
    int pid_m = (pid / npg) * GROUP_M + (pid % GROUP_M);
    int pid_n = (pid % npg) / GROUP_M;
    const int bm = pid_m << 7, bn = pid_n << 7;

    auto load_tile = [&](int t) {
        uint32_t s = sbase + (uint32_t)(t % 3) * GSTAGE;
        int k0 = t << 6;
        #pragma unroll
        for (int i = 0; i < 4; i++) {
            int idx = i*256 + tid, row = idx >> 3, c = idx & 7;
            uint32_t dst = s + row*128 + (uint32_t)((c ^ (row & 7)) << 4);
            asm volatile("cp.async.cg.shared.global [%0], [%1], 16;"
                         :: "r"(dst), "l"(A + (size_t)(bm + row)*K + k0 + c*8));
        }
        #pragma unroll
        for (int i = 0; i < 4; i++) {
            int idx = i*256 + tid, row = idx >> 3, c = idx & 7;
            int brow = bn + row; if (brow >= N) brow = N - 1;
            uint32_t dst = s + 16384u + row*128 + (uint32_t)((c ^ (row & 7)) << 4);
            asm volatile("cp.async.cg.shared.global [%0], [%1], 16;"
                         :: "r"(dst), "l"(Bw + (size_t)brow*K + k0 + c*8));
        }
    };

    float acc[4][4][4];
    zero_acc(acc);

    load_tile(0);
    asm volatile("cp.async.commit_group;" ::: "memory");
    load_tile(1);
    asm volatile("cp.async.commit_group;" ::: "memory");

    for (int t = 0; t < T; t++) {
        asm volatile("cp.async.wait_group 1;" ::: "memory");
        __syncthreads();
        if (t + 2 < T) load_tile(t + 2);
        asm volatile("cp.async.commit_group;" ::: "memory");

        uint32_t as = sbase + (uint32_t)(t % 3) * GSTAGE;
        uint32_t bs = as + 16384u;

        #pragma unroll
        for (int kk = 0; kk < 4; kk++) {
            uint32_t af[4][4];
            #pragma unroll
            for (int mt = 0; mt < 4; mt++) {
                int m  = wm*64 + mt*16 + (lane & 7) + ((lane >> 3) & 1) * 8;
                int kc = kk*2 + (lane >> 4);
                uint32_t addr = as + m*128 + (uint32_t)((kc ^ (m & 7)) << 4);
                asm volatile("ldmatrix.sync.aligned.m8n8.x4.shared.b16 {%0,%1,%2,%3}, [%4];"
                             : "=r"(af[mt][0]), "=r"(af[mt][1]),
                               "=r"(af[mt][2]), "=r"(af[mt][3]) : "r"(addr));
            }
            #pragma unroll
            for (int nt = 0; nt < 4; nt++) {
                int nrow = wn*32 + nt*8 + (lane & 7);
                int bc = kk*2 + ((lane >> 3) & 1);
                uint32_t baddr = bs + nrow*128 + (uint32_t)((bc ^ (nrow & 7)) << 4);
                uint32_t b0, b1;
                asm volatile("ldmatrix.sync.aligned.m8n8.x2.shared.b16 {%0,%1}, [%2];"
                             : "=r"(b0), "=r"(b1) : "r"(baddr));
                #pragma unroll
                for (int mt = 0; mt < 4; mt++) {
                    asm volatile(
                        "mma.sync.aligned.m16n8k16.row.col.f32.f16.f16.f32 "
                        "{%0,%1,%2,%3}, {%4,%5,%6,%7}, {%8,%9}, {%0,%1,%2,%3};"
                        : "+f"(acc[mt][nt][0]), "+f"(acc[mt][nt][1]),
                          "+f"(acc[mt][nt][2]), "+f"(acc[mt][nt][3])
                        : "r"(af[mt][0]), "r"(af[mt][1]), "r"(af[mt][2]), "r"(af[mt][3]),
                          "r"(b0), "r"(b1));
                }
            }
        }
    }

    // epilogue
    #pragma unroll
    for (int mt = 0; mt < 4; mt++) {
        int r0 = bm + wm*64 + mt*16 + (lane >> 2);
        #pragma unroll
        for (int nt = 0; nt < 4; nt++) {
            int c0 = bn + wn*32 + nt*8 + 2*(lane & 3);
            if (c0 < N) {
                float2 v0 = make_float2(acc[mt][nt][0], acc[mt][nt][1]);
                float2 v1 = make_float2(acc[mt][nt][2], acc[mt][nt][3]);
                if (mode == 3) {
                    // even col = gate, odd col = up (row-interleaved weights)
                    float r0v = v0.y * (v0.x / (1.f + expf(-v0.x)));
                    float r1v = v1.y * (v1.x / (1.f + expf(-v1.x)));
                    int half_n = N >> 1;
                    Ch[(size_t)r0*half_n + (c0 >> 1)]     = __float2half_rn(r0v);
                    Ch[(size_t)(r0+8)*half_n + (c0 >> 1)] = __float2half_rn(r1v);
                } else {
                    if (mode == 1) {
                        float2 q0 = *reinterpret_cast<const float2*>(Res + (size_t)r0*N + c0);
                        float2 q1 = *reinterpret_cast<const float2*>(Res + (size_t)(r0+8)*N + c0);
                        v0.x += q0.x; v0.y += q0.y; v1.x += q1.x; v1.y += q1.y;
                    }
                    *reinterpret_cast<float2*>(Cf + (size_t)r0*N + c0)     = v0;
                    *reinterpret_cast<float2*>(Cf + (size_t)(r0+8)*N + c0) = v1;
                }
            }
        }
    }
}

static inline int gemm_grid(int N) { return 32 * ((N + 127) >> 7); }

// ---------------- RMSNorm (fp16 output) ----------------
__global__ void rmsnorm_k(const float* __restrict__ x, const float* __restrict__ w,
                          __half* __restrict__ o)
{
    int t = blockIdx.x;
    const float* xr = x + (size_t)t*DM;
    float s = 0.f;
    for (int i = threadIdx.x; i < DM; i += 256) { float v = xr[i]; s += v*v; }
    __shared__ float red[256];
    red[threadIdx.x] = s; __syncthreads();
    for (int st = 128; st > 0; st >>= 1) {
        if (threadIdx.x < st) red[threadIdx.x] += red[threadIdx.x + st];
        __syncthreads();
    }
    float inv = rsqrtf(red[0] / (float)DM + 1e-5f);
    __half* orow = o + (size_t)t*DM;
    for (int i = threadIdx.x; i < DM; i += 256) orow[i] = __float2half_rn(xr[i]*inv*w[i]);
}

// ---------------- fused conv+SiLU (tf32 out) and dt ----------------
__global__ void convdt_k(const float* __restrict__ zx, const float* __restrict__ cw,
                         const float* __restrict__ cb, const float* __restrict__ dtb,
                         const float* __restrict__ Alog,
                         float* __restrict__ xbc, float* __restrict__ dto,
                         float* __restrict__ ao)
{
    int t = blockIdx.y;
    if (blockIdx.x < 24) {
        int c = blockIdx.x*256 + threadIdx.x;
        int l = t & (LSEQ - 1);
        const float* base = zx + (size_t)t*PROJ + 4096 + c;
        float w0 = cw[c*4+0], w1 = cw[c*4+1], w2 = cw[c*4+2], w3 = cw[c*4+3];
        float acc = cb[c] + w3*base[0];
        if (l >= 1) acc += w2*base[-(ptrdiff_t)PROJ];
        if (l >= 2) acc += w1*base[-(ptrdiff_t)(2*PROJ)];
        if (l >= 3) acc += w0*base[-(ptrdiff_t)(3*PROJ)];
        float sv = acc / (1.f + expf(-acc));
        xbc[(size_t)t*CONVD + c] = tf32r(sv);
    } else if (threadIdx.x < NH) {
        int h = threadIdx.x;
        float raw = zx[(size_t)t*PROJ + 10240 + h] + dtb[h];
        float dt = (raw > 20.f) ? raw : log1pf(expf(raw));
        dto[t*NH + h] = dt;
        ao[t*NH + h]  = -expf(Alog[h]) * dt;
    }
}

// ---------------- SSD stage 1 (tf32 tensor cores) ----------------
#define SSD1_SMEM 196608
__global__ void __launch_bounds__(256)
ssd1_k(const float* __restrict__ xbc, const float* __restrict__ dtv,
       const float* __restrict__ av, const float* __restrict__ Dv,
       float* __restrict__ Y, float* __restrict__ cso,
       float* __restrict__ gmo, float* __restrict__ states)
{
    extern __shared__ float dyn[];
    __shared__ float cs[128], dts[128], wv[128], wsum[4];
    uint32_t sb = (uint32_t)__cvta_generic_to_shared(dyn);
    uint32_t O_C = sb, O_B = sb + 65536u, O_X = sb + 131072u;

    int blk = blockIdx.x;
    int h = blk & 31, ch = (blk >> 5) & 15, b = blk >> 9;
    int t0 = b*LSEQ + ch*128;
    int g  = h >> 2;
    int tid = threadIdx.x, lane = tid & 31, warp = tid >> 5;
    int wm = warp & 1, wn = warp >> 1;

    const float* gC = xbc + (size_t)t0*CONVD + 2048 + h*128;
    const float* gB = xbc + (size_t)t0*CONVD + 1024 + g*128;
    const float* gX = xbc + (size_t)t0*CONVD + g*128;
    load_tile128(O_C, gC, CONVD, tid);
    load_tile128(O_B, gB, CONVD, tid);
    load_tile128(O_X, gX, CONVD, tid);
    asm volatile("cp.async.commit_group;" ::: "memory");

    float v = 0.f;
    if (tid < 128) {
        dts[tid] = dtv[(size_t)(t0+tid)*NH + h];
        v = av[(size_t)(t0+tid)*NH + h];
        #pragma unroll
        for (int off = 1; off < 32; off <<= 1) {
            float n = __shfl_up_sync(0xffffffffu, v, off);
            if (lane >= off) v += n;
        }
        if (lane == 31) wsum[tid >> 5] = v;
    }
    __syncthreads();
    if (tid < 128) {
        float add = 0.f;
        for (int w = 0; w < (tid >> 5); w++) add += wsum[w];
        float c = v + add;
        cs[tid] = c;
        cso[blk*128 + tid] = c;
    }
    __syncthreads();
    if (tid < 128) wv[tid] = __expf(cs[127] - cs[tid]) * dts[tid];
    if (tid == 0) gmo[blk] = expf(cs[127]);

    asm volatile("cp.async.wait_group 0;" ::: "memory");
    __syncthreads();

    float acc[4][4][4];
    zero_acc(acc);
    mma_tile128(O_C, O_B, acc, wm, wn, lane);
    __syncthreads();
    transpose128(O_X, O_C, warp, lane);
    __syncthreads();
    #pragma unroll
    for (int mt = 0; mt < 4; mt++) {
        int r0 = wm*64 + mt*16 + (lane >> 2);
        #pragma unroll
        for (int nt = 0; nt < 4; nt++) {
            int c0 = wn*32 + nt*8 + 2*(lane & 3);
            #pragma unroll
            for (int e = 0; e < 4; e++) {
                int q = r0 + (e >> 1)*8, k = c0 + (e & 1);
                float f = (q >= k) ? __expf(cs[q] - cs[k]) * dts[k] : 0.f;
                float val = tf32r(acc[mt][nt][e] * f);
                asm volatile("st.shared.f32 [%0], %1;" :: "r"(swaddr(O_X, q, k)), "f"(val));
            }
        }
    }
    __syncthreads();
    zero_acc(acc);
    mma_tile128(O_X, O_C, acc, wm, wn, lane);
    float Dh = Dv[h];
    #pragma unroll
    for (int mt = 0; mt < 4; mt++) {
        int r0 = wm*64 + mt*16 + (lane >> 2);
        #pragma unroll
        for (int nt = 0; nt < 4; nt++) {
            int c0 = wn*32 + nt*8 + 2*(lane & 3);
            #pragma unroll
            for (int e = 0; e < 4; e++) {
                int q = r0 + (e >> 1)*8, p = c0 + (e & 1);
                float xv;
                asm volatile("ld.shared.f32 %0, [%1];" : "=f"(xv) : "r"(swaddr(O_C, p, q)));
                Y[(size_t)(t0+q)*DIN + h*128 + p] = acc[mt][nt][e] + Dh*xv;
            }
        }
    }
    __syncthreads();
    transpose128(O_B, O_X, warp, lane);
    #pragma unroll
    for (int ks = 0; ks < 4; ks++) {
        int k = ks*32 + lane;
        float wk = wv[k];
        #pragma unroll
        for (int j = 0; j < 16; j++) {
            int p = warp*16 + j;
            float xv;
            asm volatile("ld.shared.f32 %0, [%1];" : "=f"(xv) : "r"(swaddr(O_C, p, k)));
            xv = tf32r(xv * wk);
            asm volatile("st.shared.f32 [%0], %1;" :: "r"(swaddr(O_C, p, k)), "f"(xv));
        }
    }
    __syncthreads();
    zero_acc(acc);
    mma_tile128(O_C, O_X, acc, wm, wn, lane);
    size_t sbase = (size_t)blk*HP*HN;
    #pragma unroll
    for (int mt = 0; mt < 4; mt++) {
        int r0 = wm*64 + mt*16 + (lane >> 2);
        #pragma unroll
        for (int nt = 0; nt < 4; nt++) {
            int c0 = wn*32 + nt*8 + 2*(lane & 3);
            *reinterpret_cast<float2*>(states + sbase + (size_t)r0*HN + c0)
                = make_float2(acc[mt][nt][0], acc[mt][nt][1]);
            *reinterpret_cast<float2*>(states + sbase + (size_t)(r0+8)*HN + c0)
                = make_float2(acc[mt][nt][2], acc[mt][nt][3]);
        }
    }
}

// ---------------- inter-chunk recurrence ----------------
__global__ void scan_k(const float* __restrict__ states, const float* __restrict__ gm,
                       float* __restrict__ prev)
{
    int bh = blockIdx.x;
    int b = bh >> 5, h = bh & 31;
    int e0 = threadIdx.x;
    float S[16];
    #pragma unroll
    for (int e = 0; e < 16; e++) S[e] = 0.f;
    for (int ch = 0; ch < NCH; ch++) {
        int blk = (b*NCH + ch)*NH + h;
        float gv = gm[blk];
        size_t base = (size_t)blk*HP*HN;
        #pragma unroll
        for (int e = 0; e < 16; e++) {
            int idx = e0 + e*1024;
            prev[base + idx] = tf32r(S[e]);
            S[e] = gv*S[e] + states[base + idx];
        }
    }
}

// ---------------- SSD stage 2 (tf32 tensor cores) + gating -> fp16 Yh ----------------
#define SSD2_SMEM 131072
__global__ void __launch_bounds__(256)
ssd2_k(const float* __restrict__ xbc, const float* __restrict__ prev,
       const float* __restrict__ csv, const float* __restrict__ zx,
       const float* __restrict__ Y, __half* __restrict__ Yh)
{
    extern __shared__ float dyn[];
    __shared__ float cs[128];
    uint32_t sb = (uint32_t)__cvta_generic_to_shared(dyn);
    uint32_t O_C = sb, O_P = sb + 65536u;

    int blk = blockIdx.x;
    int h = blk & 31, ch = (blk >> 5) & 15, b = blk >> 9;
    int t0 = b*LSEQ + ch*128;
    int tid = threadIdx.x, lane = tid & 31, warp = tid >> 5;
    int wm = warp & 1, wn = warp >> 1;

    const float* gC = xbc + (size_t)t0*CONVD + 2048 + h*128;
    size_t pbase = (size_t)blk*HP*HN;
    load_tile128(O_C, gC, CONVD, tid);
    load_tile128(O_P, prev + pbase, HN, tid);
    asm volatile("cp.async.commit_group;" ::: "memory");
    if (tid < 128) cs[tid] = csv[blk*128 + tid];
    asm volatile("cp.async.wait_group 0;" ::: "memory");
    __syncthreads();

    float acc[4][4][4];
    zero_acc(acc);
    mma_tile128(O_C, O_P, acc, wm, wn, lane);

    #pragma unroll
    for (int mt = 0; mt < 4; mt++) {
        int r0 = wm*64 + mt*16 + (lane >> 2);
        float eq0 = __expf(cs[r0]), eq1 = __expf(cs[r0 + 8]);
        #pragma unroll
        for (int nt = 0; nt < 4; nt++) {
            int c0 = wn*32 + nt*8 + 2*(lane & 3);
            #pragma unroll
            for (int half = 0; half < 2; half++) {
                int q = r0 + half*8;
                float eq = half ? eq1 : eq0;
                size_t off = (size_t)(t0+q)*DIN + h*128 + c0;
                float2 yv = *reinterpret_cast<const float2*>(Y + off);
                float2 zv = *reinterpret_cast<const float2*>(zx + (size_t)(t0+q)*PROJ + h*128 + c0);
                float s0 = zv.x / (1.f + expf(-zv.x));
                float s1 = zv.y / (1.f + expf(-zv.y));
                float a0 = acc[mt][nt][half*2+0], a1 = acc[mt][nt][half*2+1];
                *reinterpret_cast<__half2*>(Yh + off)
                    = __floats2half2_rn((yv.x + eq*a0) * s0, (yv.y + eq*a1) * s1);
            }
        }
    }
}

// ---------------- launcher ----------------
extern "C" void kernel_launch(void* const* d_in, const int* in_sizes, int n_in,
                              void* d_out, int out_size)
{
    const float* hidden = (const float*)d_in[0];
    const float* w_in   = (const float*)d_in[1];
    const float* conv_w = (const float*)d_in[2];
    const float* conv_b = (const float*)d_in[3];
    const float* A_log  = (const float*)d_in[4];
    const float* Dv     = (const float*)d_in[5];
    const float* dt_b   = (const float*)d_in[6];
    const float* w_out  = (const float*)d_in[7];
    const float* ln1    = (const float*)d_in[8];
    const float* ln2    = (const float*)d_in[9];
    const float* gate_w = (const float*)d_in[10];
    const float* up_w   = (const float*)d_in[11];
    const float* down_w = (const float*)d_in[12];
    float* out = (float*)d_out;

    float *zx, *xbc, *dt, *av, *cs, *gm, *st, *pv, *Y, *h;
    __half *hnormh, *Yh, *h2h, *uph;
    __half *winh, *wouth, *guh, *downh;
    cudaGetSymbolAddress((void**)&hnormh, d_hnormh);
    cudaGetSymbolAddress((void**)&zx,     d_zx);
    cudaGetSymbolAddress((void**)&xbc,    d_xbc);
    cudaGetSymbolAddress((void**)&dt,     d_dt);
    cudaGetSymbolAddress((void**)&av,     d_av);
    cudaGetSymbolAddress((void**)&cs,     d_cs);
    cudaGetSymbolAddress((void**)&gm,     d_gm);
    cudaGetSymbolAddress((void**)&st,     d_states);
    cudaGetSymbolAddress((void**)&pv,     d_prev);
    cudaGetSymbolAddress((void**)&Y,      d_Y);
    cudaGetSymbolAddress((void**)&Yh,     d_Yh);
    cudaGetSymbolAddress((void**)&h,      d_h);
    cudaGetSymbolAddress((void**)&h2h,    d_h2h);
    cudaGetSymbolAddress((void**)&uph,    d_uph);
    cudaGetSymbolAddress((void**)&winh,   d_win_h);
    cudaGetSymbolAddress((void**)&wouth,  d_wout_h);
    cudaGetSymbolAddress((void**)&guh,    d_gu_h);
    cudaGetSymbolAddress((void**)&downh,  d_down_h);

    cudaFuncSetAttribute(gemm_h, cudaFuncAttributeMaxDynamicSharedMemorySize, GSMEM_DYN);
    cudaFuncSetAttribute(ssd1_k, cudaFuncAttributeMaxDynamicSharedMemorySize, SSD1_SMEM);
    cudaFuncSetAttribute(ssd2_k, cudaFuncAttributeMaxDynamicSharedMemorySize, SSD2_SMEM);

    // 0) convert weights to fp16 (gate+up row-interleaved)
    to_half_k<<<1024, 256>>>(w_in,   winh,  (PROJ*DM)/4);
    to_half_k<<<1024, 256>>>(w_out,  wouth, (DM*DIN)/4);
    interleave_half_k<<<2048, 256>>>(gate_w, up_w, guh, (2*INTERD*DM)/4);
    to_half_k<<<1024, 256>>>(down_w, downh, (DM*INTERD)/4);

    // 1) pre-norm (fp16 output)
    rmsnorm_k<<<TKN, 256>>>(hidden, ln1, hnormh);
    // 2) in_proj
    gemm_h<<<gemm_grid(PROJ), 256, GSMEM_DYN>>>(hnormh, winh, nullptr, zx, nullptr, PROJ, DM, 0);
    // 3+4) fused conv + dt
    convdt_k<<<dim3(25, TKN), 256>>>(zx, conv_w, conv_b, dt_b, A_log, xbc, dt, av);
    // 5) SSD stage 1 (tf32 tensor cores)
    ssd1_k<<<NBLK, 256, SSD1_SMEM>>>(xbc, dt, av, Dv, Y, cs, gm, st);
    // 6) inter-chunk recurrence
    scan_k<<<NB*NH, 1024>>>(st, gm, pv);
    // 7) SSD stage 2 + gating -> fp16 Yh
    ssd2_k<<<NBLK, 256, SSD2_SMEM>>>(xbc, pv, cs, zx, Y, Yh);
    // 8) out_proj + residual
    gemm_h<<<gemm_grid(DM), 256, GSMEM_DYN>>>(Yh, wouth, hidden, h, nullptr, DM, DIN, 1);
    // 9) second norm (fp16 output)
    rmsnorm_k<<<TKN, 256>>>(h, ln2, h2h);
    // 10) fused gate+up GEMM -> uph = silu(gate)*up (fp16)
    gemm_h<<<gemm_grid(2*INTERD), 256, GSMEM_DYN>>>(h2h, guh, nullptr, nullptr, uph,
                                                    2*INTERD, DM, 3);
    // 11) down_proj + residual -> out
    gemm_h<<<gemm_grid(DM), 256, GSMEM_DYN>>>(uph, downh, h, out, nullptr, DM, INTERD, 1);
}